// round 1
// baseline (speedup 1.0000x reference)
#include <cuda_runtime.h>
#include <cuda_fp16.h>
#include <mma.h>

using namespace nvcuda;

#define B_  2
#define S_  4096
#define D_  1024
#define H_  16
#define DK_ 64
#define BS_ (B_*S_)          // 8192 rows

// ---------------- device scratch (static, no allocations) ----------------
__device__ __half g_qh[BS_*D_];
__device__ __half g_kh[BS_*D_];
__device__ __half g_vh[BS_*D_];
__device__ __half g_wq[D_*D_];
__device__ __half g_wk[D_*D_];
__device__ __half g_wv[D_*D_];
__device__ __half g_wo[D_*D_];
__device__ __half g_Q[BS_*D_];    // [B,H,S,DK]
__device__ __half g_K[BS_*D_];    // [B,H,S,DK]
__device__ __half g_V[BS_*D_];    // [B,H,S,DK]
__device__ __half g_ctx[BS_*D_];  // [B,S,D]
__device__ unsigned g_maskbits[S_*S_/32];

// ---------------- fp32 -> fp16 convert ----------------
__global__ void f2h_kernel(const float4* __restrict__ src, __half2* __restrict__ dst, int n4) {
    int i = blockIdx.x * blockDim.x + threadIdx.x;
    if (i < n4) {
        float4 v = src[i];
        dst[2*i + 0] = __floats2half2_rn(v.x, v.y);
        dst[2*i + 1] = __floats2half2_rn(v.z, v.w);
    }
}

// ---------------- mask -> bitmask ----------------
__global__ void maskpack_kernel(const int* __restrict__ mask, unsigned* __restrict__ out, int n) {
    int i = blockIdx.x * blockDim.x + threadIdx.x;
    unsigned b = __ballot_sync(0xffffffffu, (i < n) && (mask[i] != 0));
    if (((threadIdx.x & 31) == 0) && i < n) out[i >> 5] = b;
}

// ---------------- GEMM: C[M,1024] = A[M,1024] * W[1024,1024]^T ----------------
// HEAD_OUT: write half, scattered to [B,H,S,DK]. else: write fp32 [M,1024].
template <bool HEAD_OUT>
__global__ void __launch_bounds__(256) gemm_kernel(
    const __half* __restrict__ A,
    const __half* __restrict__ W,
    __half* __restrict__ outH,
    float* __restrict__ outF)
{
    const int K = 1024;
    __shared__ __half As[128][40];
    __shared__ __half Bs[128][40];
    __shared__ float  stage[8][16*20];

    int tid  = threadIdx.x;
    int wid  = tid >> 5;
    int lane = tid & 31;
    int bm = blockIdx.y * 128;
    int bn = blockIdx.x * 128;
    int warp_m = wid >> 1;   // 0..3 -> 32 rows each
    int warp_n = wid & 1;    // 0..1 -> 64 cols each

    wmma::fragment<wmma::accumulator, 16, 16, 16, float> acc[2][4];
    #pragma unroll
    for (int i = 0; i < 2; i++)
        #pragma unroll
        for (int j = 0; j < 4; j++)
            wmma::fill_fragment(acc[i][j], 0.0f);

    int lr = tid >> 2;          // 0..63
    int lc = (tid & 3) * 8;     // 0,8,16,24

    for (int k0 = 0; k0 < K; k0 += 32) {
        *(uint4*)&As[lr     ][lc] = *(const uint4*)&A[(bm + lr     ) * K + k0 + lc];
        *(uint4*)&As[lr + 64][lc] = *(const uint4*)&A[(bm + lr + 64) * K + k0 + lc];
        *(uint4*)&Bs[lr     ][lc] = *(const uint4*)&W[(bn + lr     ) * K + k0 + lc];
        *(uint4*)&Bs[lr + 64][lc] = *(const uint4*)&W[(bn + lr + 64) * K + k0 + lc];
        __syncthreads();
        #pragma unroll
        for (int kk = 0; kk < 2; kk++) {
            wmma::fragment<wmma::matrix_a, 16, 16, 16, __half, wmma::row_major> af[2];
            wmma::fragment<wmma::matrix_b, 16, 16, 16, __half, wmma::col_major> bf[4];
            #pragma unroll
            for (int i = 0; i < 2; i++)
                wmma::load_matrix_sync(af[i], &As[warp_m*32 + i*16][kk*16], 40);
            #pragma unroll
            for (int j = 0; j < 4; j++)
                wmma::load_matrix_sync(bf[j], &Bs[warp_n*64 + j*16][kk*16], 40);
            #pragma unroll
            for (int i = 0; i < 2; i++)
                #pragma unroll
                for (int j = 0; j < 4; j++)
                    wmma::mma_sync(acc[i][j], af[i], bf[j], acc[i][j]);
        }
        __syncthreads();
    }

    if (!HEAD_OUT) {
        #pragma unroll
        for (int i = 0; i < 2; i++)
            #pragma unroll
            for (int j = 0; j < 4; j++) {
                int m0 = bm + warp_m*32 + i*16;
                int n0 = bn + warp_n*64 + j*16;
                wmma::store_matrix_sync(outF + (size_t)m0 * 1024 + n0, acc[i][j], 1024,
                                        wmma::mem_row_major);
            }
    } else {
        #pragma unroll
        for (int i = 0; i < 2; i++)
            #pragma unroll
            for (int j = 0; j < 4; j++) {
                wmma::store_matrix_sync(&stage[wid][0], acc[i][j], 20, wmma::mem_row_major);
                __syncwarp();
                int m0 = bm + warp_m*32 + i*16;
                int e0 = bn + warp_n*64 + j*16;
                int h   = e0 >> 6;
                int dk0 = e0 & 63;
                int b   = m0 >> 12;       // blocks never cross batch (4096 % 128 == 0)
                int s0  = m0 & 4095;
                int r  = lane >> 1;
                int c0 = (lane & 1) * 8;
                const float* srow = &stage[wid][r * 20 + c0];
                __half* drow = outH + ((size_t)(b * H_ + h) * S_ + s0 + r) * DK_ + dk0 + c0;
                #pragma unroll
                for (int c = 0; c < 8; c++) drow[c] = __float2half_rn(srow[c]);
                __syncwarp();
            }
    }
}

// ---------------- Flash attention ----------------
// grid: (S/64, B*H). 256 threads. 64 queries per block, stream keys in 64-tiles.
#define FA_BM 64
#define FA_BN 64
#define LDH 72   // half stride (144B, 16B-aligned)
#define LDF 68   // float stride (272B, 16B-aligned)

#define SMEM_FLASH (3*64*LDH*2 + 2*64*LDF*4 + 3*64*4)

__global__ void __launch_bounds__(256) flash_kernel(
    const __half* __restrict__ Qp,
    const __half* __restrict__ Kp,
    const __half* __restrict__ Vp,
    const unsigned* __restrict__ maskbits,
    __half* __restrict__ ctx)
{
    extern __shared__ char sm_raw[];
    __half* Ks = (__half*)sm_raw;                 // [64][72]
    __half* Vs = Ks + 64*LDH;
    __half* Ps = Vs + 64*LDH;
    float*  Ss = (float*)(Ps + 64*LDH);           // [64][68] (scores, then PV stage)
    float*  Os = Ss + 64*LDF;                     // [64][68]
    float*  m_s  = Os + 64*LDF;
    float*  l_s  = m_s + 64;
    float*  al_s = l_s + 64;

    int tid = threadIdx.x;
    int wid = tid >> 5;
    int q0 = blockIdx.x * FA_BM;
    int bh = blockIdx.y;                          // b*H + h
    const __half* Qbase = Qp + ((size_t)bh * S_ + q0) * DK_;
    const __half* Kbase = Kp + (size_t)bh * S_ * DK_;
    const __half* Vbase = Vp + (size_t)bh * S_ * DK_;

    for (int i = tid; i < 64*LDF; i += 256) Os[i] = 0.0f;
    if (tid < 64) { m_s[tid] = -1e30f; l_s[tid] = 0.0f; }

    // stage Q through Ks, keep it in persistent A-fragments
    {
        int r = tid >> 3, c = (tid & 7) * 8;
        *(uint4*)&Ks[ r      *LDH + c] = *(const uint4*)&Qbase[ r      * DK_ + c];
        *(uint4*)&Ks[(r + 32)*LDH + c] = *(const uint4*)&Qbase[(r + 32) * DK_ + c];
    }
    __syncthreads();

    int tm  = wid >> 1;         // row tile 0..3
    int tn0 = (wid & 1) * 2;    // col tile base 0 or 2

    wmma::fragment<wmma::matrix_a, 16, 16, 16, __half, wmma::row_major> qf[4];
    #pragma unroll
    for (int kk = 0; kk < 4; kk++)
        wmma::load_matrix_sync(qf[kk], &Ks[tm*16*LDH + kk*16], LDH);
    __syncthreads();

    for (int j0 = 0; j0 < S_; j0 += FA_BN) {
        // load K/V tiles
        {
            int r = tid >> 3, c = (tid & 7) * 8;
            *(uint4*)&Ks[ r      *LDH + c] = *(const uint4*)&Kbase[(j0 + r     ) * DK_ + c];
            *(uint4*)&Ks[(r + 32)*LDH + c] = *(const uint4*)&Kbase[(j0 + r + 32) * DK_ + c];
            *(uint4*)&Vs[ r      *LDH + c] = *(const uint4*)&Vbase[(j0 + r     ) * DK_ + c];
            *(uint4*)&Vs[(r + 32)*LDH + c] = *(const uint4*)&Vbase[(j0 + r + 32) * DK_ + c];
        }
        __syncthreads();

        // S = (Q K^T) * 0.125
        wmma::fragment<wmma::accumulator, 16, 16, 16, float> sc[2];
        wmma::fill_fragment(sc[0], 0.0f);
        wmma::fill_fragment(sc[1], 0.0f);
        #pragma unroll
        for (int kk = 0; kk < 4; kk++) {
            #pragma unroll
            for (int j = 0; j < 2; j++) {
                wmma::fragment<wmma::matrix_b, 16, 16, 16, __half, wmma::col_major> kf;
                wmma::load_matrix_sync(kf, &Ks[(tn0 + j)*16*LDH + kk*16], LDH);
                wmma::mma_sync(sc[j], qf[kk], kf, sc[j]);
            }
        }
        #pragma unroll
        for (int j = 0; j < 2; j++) {
            #pragma unroll
            for (int t = 0; t < sc[j].num_elements; t++) sc[j].x[t] *= 0.125f;
            wmma::store_matrix_sync(&Ss[tm*16*LDF + (tn0 + j)*16], sc[j], LDF, wmma::mem_row_major);
        }
        __syncthreads();

        // masked online softmax: 4 threads per row, 16 cols each
        {
            int r = tid >> 2, quad = tid & 3, c0 = quad * 16;
            int q = q0 + r;
            unsigned wbits = maskbits[((size_t)q * S_ + j0 + c0) >> 5];
            int shift = c0 & 31;   // 0 or 16
            float sv[16];
            float mx = -1e30f;
            #pragma unroll
            for (int c = 0; c < 16; c++) {
                float s = Ss[r*LDF + c0 + c];
                if (!((wbits >> (shift + c)) & 1u)) s = -1e9f;
                sv[c] = s;
                mx = fmaxf(mx, s);
            }
            mx = fmaxf(mx, __shfl_xor_sync(0xffffffffu, mx, 1));
            mx = fmaxf(mx, __shfl_xor_sync(0xffffffffu, mx, 2));
            float m_old = m_s[r];
            float m_new = fmaxf(m_old, mx);
            float alpha = __expf(m_old - m_new);
            float lsum = 0.0f;
            #pragma unroll
            for (int c = 0; c < 16; c++) {
                float p = __expf(sv[c] - m_new);
                lsum += p;
                Ps[r*LDH + c0 + c] = __float2half_rn(p);
            }
            lsum += __shfl_xor_sync(0xffffffffu, lsum, 1);
            lsum += __shfl_xor_sync(0xffffffffu, lsum, 2);
            if (quad == 0) {
                m_s[r]  = m_new;
                l_s[r]  = l_s[r] * alpha + lsum;
                al_s[r] = alpha;
            }
        }
        __syncthreads();

        // PV = P * V (fresh accum), stage into Ss
        wmma::fragment<wmma::accumulator, 16, 16, 16, float> pv[2];
        wmma::fill_fragment(pv[0], 0.0f);
        wmma::fill_fragment(pv[1], 0.0f);
        #pragma unroll
        for (int kk = 0; kk < 4; kk++) {
            wmma::fragment<wmma::matrix_a, 16, 16, 16, __half, wmma::row_major> pf;
            wmma::load_matrix_sync(pf, &Ps[tm*16*LDH + kk*16], LDH);
            #pragma unroll
            for (int j = 0; j < 2; j++) {
                wmma::fragment<wmma::matrix_b, 16, 16, 16, __half, wmma::row_major> vf;
                wmma::load_matrix_sync(vf, &Vs[kk*16*LDH + (tn0 + j)*16], LDH);
                wmma::mma_sync(pv[j], pf, vf, pv[j]);
            }
        }
        #pragma unroll
        for (int j = 0; j < 2; j++)
            wmma::store_matrix_sync(&Ss[tm*16*LDF + (tn0 + j)*16], pv[j], LDF, wmma::mem_row_major);
        __syncthreads();

        // O = O*alpha + PV
        {
            int r = tid >> 2, c0 = (tid & 3) * 16;
            float a = al_s[r];
            #pragma unroll
            for (int c = 0; c < 16; c++)
                Os[r*LDF + c0 + c] = Os[r*LDF + c0 + c] * a + Ss[r*LDF + c0 + c];
        }
        __syncthreads();
    }

    // epilogue: ctx[b, s, h*64 + d] = O / l
    {
        int r = tid >> 2, c0 = (tid & 3) * 16;
        float inv = 1.0f / l_s[r];
        int b = bh >> 4, h = bh & 15;
        __half* dst = ctx + ((size_t)(b * S_ + q0 + r)) * D_ + h * DK_ + c0;
        #pragma unroll
        for (int c = 0; c < 16; c++)
            dst[c] = __float2half_rn(Os[r*LDF + c0 + c] * inv);
    }
}

// ---------------- launch ----------------
static void* symaddr(const void* sym) {
    void* p = nullptr;
    cudaGetSymbolAddress(&p, sym);
    return p;
}

extern "C" void kernel_launch(void* const* d_in, const int* in_sizes, int n_in,
                              void* d_out, int out_size)
{
    const float* q    = (const float*)d_in[0];
    const float* k    = (const float*)d_in[1];
    const float* v    = (const float*)d_in[2];
    const int*   mask = (const int*)  d_in[3];
    const float* w_q  = (const float*)d_in[4];
    const float* w_k  = (const float*)d_in[5];
    const float* w_v  = (const float*)d_in[6];
    const float* w_o  = (const float*)d_in[7];

    __half* qh = (__half*)symaddr(g_qh);
    __half* kh = (__half*)symaddr(g_kh);
    __half* vh = (__half*)symaddr(g_vh);
    __half* wq = (__half*)symaddr(g_wq);
    __half* wk = (__half*)symaddr(g_wk);
    __half* wv = (__half*)symaddr(g_wv);
    __half* wo = (__half*)symaddr(g_wo);
    __half* Qp = (__half*)symaddr(g_Q);
    __half* Kp = (__half*)symaddr(g_K);
    __half* Vp = (__half*)symaddr(g_V);
    __half* cx = (__half*)symaddr(g_ctx);
    unsigned* mb = (unsigned*)symaddr(g_maskbits);

    // converts
    int n4 = BS_ * D_ / 4;
    f2h_kernel<<<n4/256, 256>>>((const float4*)q, (__half2*)qh, n4);
    f2h_kernel<<<n4/256, 256>>>((const float4*)k, (__half2*)kh, n4);
    f2h_kernel<<<n4/256, 256>>>((const float4*)v, (__half2*)vh, n4);
    int w4 = D_ * D_ / 4;
    f2h_kernel<<<w4/256, 256>>>((const float4*)w_q, (__half2*)wq, w4);
    f2h_kernel<<<w4/256, 256>>>((const float4*)w_k, (__half2*)wk, w4);
    f2h_kernel<<<w4/256, 256>>>((const float4*)w_v, (__half2*)wv, w4);
    f2h_kernel<<<w4/256, 256>>>((const float4*)w_o, (__half2*)wo, w4);

    // mask bitpack
    maskpack_kernel<<<(S_*S_)/256, 256>>>(mask, mb, S_*S_);

    // projections -> head-major Q/K/V
    dim3 gg(D_/128, BS_/128);
    gemm_kernel<true><<<gg, 256>>>(qh, wq, Qp, nullptr);
    gemm_kernel<true><<<gg, 256>>>(kh, wk, Kp, nullptr);
    gemm_kernel<true><<<gg, 256>>>(vh, wv, Vp, nullptr);

    // flash attention
    cudaFuncSetAttribute(flash_kernel, cudaFuncAttributeMaxDynamicSharedMemorySize, SMEM_FLASH);
    flash_kernel<<<dim3(S_/FA_BM, B_*H_), 256, SMEM_FLASH>>>(Qp, Kp, Vp, mb, cx);

    // output projection (fp32 out)
    gemm_kernel<false><<<gg, 256>>>(cx, wo, nullptr, (float*)d_out);
}

// round 2
// speedup vs baseline: 1.7627x; 1.7627x over previous
#include <cuda_runtime.h>
#include <cuda_fp16.h>
#include <mma.h>

using namespace nvcuda;

#define B_  2
#define S_  4096
#define D_  1024
#define H_  16
#define DK_ 64
#define BS_ (B_*S_)          // 8192 rows

// ---------------- device scratch (static, no allocations) ----------------
__device__ __half g_qh[BS_*D_];
__device__ __half g_kh[BS_*D_];
__device__ __half g_vh[BS_*D_];
__device__ __half g_wq[D_*D_];
__device__ __half g_wk[D_*D_];
__device__ __half g_wv[D_*D_];
__device__ __half g_wo[D_*D_];
__device__ __half g_Q[BS_*D_];    // [B,H,S,DK]
__device__ __half g_K[BS_*D_];    // [B,H,S,DK]
__device__ __half g_V[BS_*D_];    // [B,H,S,DK]
__device__ __half g_ctx[BS_*D_];  // [B,S,D]
__device__ unsigned g_maskbits[S_*S_/32];

// ---------------- small PTX helpers ----------------
__device__ __forceinline__ unsigned smem_u32(const void* p) {
    return (unsigned)__cvta_generic_to_shared(p);
}
__device__ __forceinline__ void cp_async16(void* dst, const void* src) {
    asm volatile("cp.async.cg.shared.global [%0], [%1], 16;"
                 :: "r"(smem_u32(dst)), "l"(src));
}
#define CP_COMMIT() asm volatile("cp.async.commit_group;")
#define CP_WAIT0()  asm volatile("cp.async.wait_group 0;")

__device__ __forceinline__ void ldsm_x4(unsigned& r0, unsigned& r1, unsigned& r2, unsigned& r3,
                                        unsigned a) {
    asm volatile("ldmatrix.sync.aligned.m8n8.x4.shared.b16 {%0,%1,%2,%3},[%4];"
                 : "=r"(r0), "=r"(r1), "=r"(r2), "=r"(r3) : "r"(a));
}
__device__ __forceinline__ void ldsm_x4t(unsigned& r0, unsigned& r1, unsigned& r2, unsigned& r3,
                                         unsigned a) {
    asm volatile("ldmatrix.sync.aligned.m8n8.x4.trans.shared.b16 {%0,%1,%2,%3},[%4];"
                 : "=r"(r0), "=r"(r1), "=r"(r2), "=r"(r3) : "r"(a));
}
__device__ __forceinline__ void mma16816(float* c, const unsigned a[4], unsigned b0, unsigned b1) {
    asm volatile("mma.sync.aligned.m16n8k16.row.col.f32.f16.f16.f32 "
                 "{%0,%1,%2,%3},{%4,%5,%6,%7},{%8,%9},{%0,%1,%2,%3};"
                 : "+f"(c[0]), "+f"(c[1]), "+f"(c[2]), "+f"(c[3])
                 : "r"(a[0]), "r"(a[1]), "r"(a[2]), "r"(a[3]), "r"(b0), "r"(b1));
}
__device__ __forceinline__ unsigned packh2(float lo, float hi) {
    __half2 h = __floats2half2_rn(lo, hi);
    return *(unsigned*)&h;
}

// ---------------- fp32 -> fp16 convert ----------------
__global__ void f2h_kernel(const float4* __restrict__ src, __half2* __restrict__ dst, int n4) {
    int i = blockIdx.x * blockDim.x + threadIdx.x;
    if (i < n4) {
        float4 v = src[i];
        dst[2*i + 0] = __floats2half2_rn(v.x, v.y);
        dst[2*i + 1] = __floats2half2_rn(v.z, v.w);
    }
}

// ---------------- mask -> bitmask ----------------
__global__ void maskpack_kernel(const int* __restrict__ mask, unsigned* __restrict__ out, int n) {
    int i = blockIdx.x * blockDim.x + threadIdx.x;
    unsigned b = __ballot_sync(0xffffffffu, (i < n) && (mask[i] != 0));
    if (((threadIdx.x & 31) == 0) && i < n) out[i >> 5] = b;
}

// ---------------- GEMM: C[M,1024] = A[M,1024] * W[1024,1024]^T ----------------
// 2-stage cp.async pipeline, 128x128 tile, k-step 32.
// HEAD_OUT: write half, scattered to [B,H,S,DK]. else: write fp32 [M,1024].
template <bool HEAD_OUT>
__global__ void __launch_bounds__(256) gemm_kernel(
    const __half* __restrict__ A,
    const __half* __restrict__ W,
    __half* __restrict__ outH,
    float* __restrict__ outF)
{
    extern __shared__ __half smem[];    // [As0|Bs0|As1|Bs1], each 128*40 halfs = 40960 B total

    int tid  = threadIdx.x;
    int wid  = tid >> 5;
    int lane = tid & 31;
    int bm = blockIdx.y * 128;
    int bn = blockIdx.x * 128;
    int warp_m = wid >> 1;   // 0..3 -> 32 rows each
    int warp_n = wid & 1;    // 0..1 -> 64 cols each

    wmma::fragment<wmma::accumulator, 16, 16, 16, float> acc[2][4];
    #pragma unroll
    for (int i = 0; i < 2; i++)
        #pragma unroll
        for (int j = 0; j < 4; j++)
            wmma::fill_fragment(acc[i][j], 0.0f);

    auto ldst = [&](int k0, int s) {
        __half* As = smem + s * 10240;
        __half* Bs = As + 5120;
        #pragma unroll
        for (int i = 0; i < 2; i++) {
            int c = tid + 256 * i;              // 0..511
            int r = c >> 2, coff = (c & 3) * 8;
            cp_async16(&As[r*40 + coff], &A[(size_t)(bm + r) * 1024 + k0 + coff]);
        }
        #pragma unroll
        for (int i = 0; i < 2; i++) {
            int c = tid + 256 * i;
            int r = c >> 2, coff = (c & 3) * 8;
            cp_async16(&Bs[r*40 + coff], &W[(size_t)(bn + r) * 1024 + k0 + coff]);
        }
    };

    ldst(0, 0); CP_COMMIT();

    for (int it = 0; it < 32; it++) {
        CP_WAIT0();
        __syncthreads();
        if (it < 31) ldst((it + 1) * 32, (it + 1) & 1);
        CP_COMMIT();

        const __half* As = smem + (it & 1) * 10240;
        const __half* Bs = As + 5120;
        #pragma unroll
        for (int kk = 0; kk < 2; kk++) {
            wmma::fragment<wmma::matrix_a, 16, 16, 16, __half, wmma::row_major> af[2];
            wmma::fragment<wmma::matrix_b, 16, 16, 16, __half, wmma::col_major> bf[4];
            #pragma unroll
            for (int i = 0; i < 2; i++)
                wmma::load_matrix_sync(af[i], &As[(warp_m*32 + i*16)*40 + kk*16], 40);
            #pragma unroll
            for (int j = 0; j < 4; j++)
                wmma::load_matrix_sync(bf[j], &Bs[(warp_n*64 + j*16)*40 + kk*16], 40);
            #pragma unroll
            for (int i = 0; i < 2; i++)
                #pragma unroll
                for (int j = 0; j < 4; j++)
                    wmma::mma_sync(acc[i][j], af[i], bf[j], acc[i][j]);
        }
    }
    __syncthreads();   // before aliasing smem as stage

    if (!HEAD_OUT) {
        #pragma unroll
        for (int i = 0; i < 2; i++)
            #pragma unroll
            for (int j = 0; j < 4; j++) {
                int m0 = bm + warp_m*32 + i*16;
                int n0 = bn + warp_n*64 + j*16;
                wmma::store_matrix_sync(outF + (size_t)m0 * 1024 + n0, acc[i][j], 1024,
                                        wmma::mem_row_major);
            }
    } else {
        float* mystage = (float*)smem + wid * 320;   // 16x20
        #pragma unroll
        for (int i = 0; i < 2; i++)
            #pragma unroll
            for (int j = 0; j < 4; j++) {
                wmma::store_matrix_sync(mystage, acc[i][j], 20, wmma::mem_row_major);
                __syncwarp();
                int m0 = bm + warp_m*32 + i*16;
                int e0 = bn + warp_n*64 + j*16;
                int h   = e0 >> 6;
                int dk0 = e0 & 63;
                int b   = m0 >> 12;
                int s0  = m0 & 4095;
                int r  = lane >> 1;
                int c0 = (lane & 1) * 8;
                const float* srow = &mystage[r * 20 + c0];
                __half* drow = outH + ((size_t)(b * H_ + h) * S_ + s0 + r) * DK_ + dk0 + c0;
                #pragma unroll
                for (int c = 0; c < 8; c++) drow[c] = __float2half_rn(srow[c]);
                __syncwarp();
            }
    }
}

// ---------------- Flash attention v2: register-resident, mma.sync ----------------
// grid (S/128, B*H), 256 threads (8 warps), each warp owns 16 q-rows.
// K/V tiles of 64 keys, 2-stage cp.async double buffer. S/P/O all in registers.
#define FBM 128
#define FBN 64
#define FLD 72                 // half stride (144 B) -> conflict-free ldmatrix
#define FSTG (64*FLD)          // halfs per K (or V) tile
#define SCALE_LOG2E 0.180336879f   // 0.125 * log2(e)

__global__ void __launch_bounds__(256) flash2_kernel(
    const __half* __restrict__ Qp,
    const __half* __restrict__ Kp,
    const __half* __restrict__ Vp,
    const unsigned* __restrict__ maskbits,
    __half* __restrict__ ctx)
{
    __shared__ __half sm[2 * 2 * FSTG];   // [K0|V0|K1|V1] = 36864 B

    int tid  = threadIdx.x;
    int lane = tid & 31;
    int wid  = tid >> 5;
    int gr   = lane >> 2;      // row-in-16 group (rows gr and gr+8)
    int cc   = lane & 3;       // col pair selector

    int q0 = blockIdx.x * FBM;
    int bh = blockIdx.y;
    const __half* Qbase = Qp + ((size_t)bh * S_ + q0) * DK_;
    const __half* Kbase = Kp + (size_t)bh * S_ * DK_;
    const __half* Vbase = Vp + (size_t)bh * S_ * DK_;

    // ---- stage Q (128x64) through smem, ldmatrix into persistent A frags ----
    #pragma unroll
    for (int i = 0; i < 4; i++) {
        int c = tid + 256 * i;               // 0..1023
        int r = c >> 3, col = (c & 7) * 8;
        *(uint4*)&sm[r*FLD + col] = *(const uint4*)&Qbase[r*DK_ + col];
    }
    __syncthreads();

    unsigned qf[4][4];
    {
        int rbase = wid * 16;
        #pragma unroll
        for (int kk = 0; kk < 4; kk++) {
            unsigned addr = smem_u32(&sm[(rbase + (lane & 15))*FLD + (lane >> 4)*8 + kk*16]);
            ldsm_x4(qf[kk][0], qf[kk][1], qf[kk][2], qf[kk][3], addr);
        }
    }
    __syncthreads();

    // ---- per-thread softmax state ----
    float o[8][4];
    #pragma unroll
    for (int j = 0; j < 8; j++) { o[j][0]=0.f; o[j][1]=0.f; o[j][2]=0.f; o[j][3]=0.f; }
    float m_lo = -1e30f, m_hi = -1e30f, l_lo = 0.f, l_hi = 0.f;

    int qlo = q0 + wid*16 + gr;
    const unsigned* mrow_lo = maskbits + (size_t)qlo * (S_/32);
    const unsigned* mrow_hi = mrow_lo + 8 * (S_/32);

    auto load_kv = [&](int j0, int s) {
        __half* Ks = sm + s * 2 * FSTG;
        __half* Vs = Ks + FSTG;
        #pragma unroll
        for (int i = 0; i < 2; i++) {
            int c = tid + 256 * i;           // 0..511
            int r = c >> 3, col = (c & 7) * 8;
            cp_async16(&Ks[r*FLD + col], &Kbase[(size_t)(j0 + r)*DK_ + col]);
        }
        #pragma unroll
        for (int i = 0; i < 2; i++) {
            int c = tid + 256 * i;
            int r = c >> 3, col = (c & 7) * 8;
            cp_async16(&Vs[r*FLD + col], &Vbase[(size_t)(j0 + r)*DK_ + col]);
        }
    };

    load_kv(0, 0); CP_COMMIT();

    for (int it = 0; it < S_/FBN; it++) {
        int j0 = it * FBN;
        CP_WAIT0();
        __syncthreads();
        if (it + 1 < S_/FBN) load_kv(j0 + FBN, (it + 1) & 1);
        CP_COMMIT();

        const __half* Ks = sm + (it & 1) * 2 * FSTG;
        const __half* Vs = Ks + FSTG;

        // ---- S = Q K^T ----
        float sc[8][4];
        #pragma unroll
        for (int j = 0; j < 8; j++) { sc[j][0]=0.f; sc[j][1]=0.f; sc[j][2]=0.f; sc[j][3]=0.f; }
        #pragma unroll
        for (int j = 0; j < 8; j++) {
            #pragma unroll
            for (int kk = 0; kk < 4; kk += 2) {
                unsigned b0, b1, b2, b3;
                unsigned addr = smem_u32(&Ks[(j*8 + (lane & 7))*FLD + kk*16 + (lane >> 3)*8]);
                ldsm_x4(b0, b1, b2, b3, addr);
                mma16816(sc[j], qf[kk],   b0, b1);
                mma16816(sc[j], qf[kk+1], b2, b3);
            }
        }

        // ---- mask + scale + row max ----
        unsigned long long bm_lo = *(const unsigned long long*)(mrow_lo + (j0 >> 5));
        unsigned long long bm_hi = *(const unsigned long long*)(mrow_hi + (j0 >> 5));
        float mxl = -1e30f, mxh = -1e30f;
        #pragma unroll
        for (int j = 0; j < 8; j++) {
            int t0 = j*8 + 2*cc;
            float s0 = ((bm_lo >> t0)     & 1ull) ? sc[j][0]*SCALE_LOG2E : -6e8f;
            float s1 = ((bm_lo >> (t0+1)) & 1ull) ? sc[j][1]*SCALE_LOG2E : -6e8f;
            float s2 = ((bm_hi >> t0)     & 1ull) ? sc[j][2]*SCALE_LOG2E : -6e8f;
            float s3 = ((bm_hi >> (t0+1)) & 1ull) ? sc[j][3]*SCALE_LOG2E : -6e8f;
            sc[j][0]=s0; sc[j][1]=s1; sc[j][2]=s2; sc[j][3]=s3;
            mxl = fmaxf(mxl, fmaxf(s0, s1));
            mxh = fmaxf(mxh, fmaxf(s2, s3));
        }
        mxl = fmaxf(mxl, __shfl_xor_sync(0xffffffffu, mxl, 1));
        mxl = fmaxf(mxl, __shfl_xor_sync(0xffffffffu, mxl, 2));
        mxh = fmaxf(mxh, __shfl_xor_sync(0xffffffffu, mxh, 1));
        mxh = fmaxf(mxh, __shfl_xor_sync(0xffffffffu, mxh, 2));

        float mnl = fmaxf(m_lo, mxl), mnh = fmaxf(m_hi, mxh);
        float al = exp2f(m_lo - mnl), ah = exp2f(m_hi - mnh);
        m_lo = mnl; m_hi = mnh;

        // ---- p = 2^(s-m), pack to fp16 A-frags, accumulate l ----
        unsigned pl[8], ph[8];
        float sl = 0.f, sh = 0.f;
        #pragma unroll
        for (int j = 0; j < 8; j++) {
            float p0 = exp2f(sc[j][0] - mnl), p1 = exp2f(sc[j][1] - mnl);
            float p2 = exp2f(sc[j][2] - mnh), p3 = exp2f(sc[j][3] - mnh);
            sl += p0 + p1; sh += p2 + p3;
            pl[j] = packh2(p0, p1);
            ph[j] = packh2(p2, p3);
        }
        sl += __shfl_xor_sync(0xffffffffu, sl, 1);
        sl += __shfl_xor_sync(0xffffffffu, sl, 2);
        sh += __shfl_xor_sync(0xffffffffu, sh, 1);
        sh += __shfl_xor_sync(0xffffffffu, sh, 2);
        l_lo = l_lo * al + sl;
        l_hi = l_hi * ah + sh;

        // ---- rescale O, then O += P V ----
        #pragma unroll
        for (int j = 0; j < 8; j++) {
            o[j][0] *= al; o[j][1] *= al; o[j][2] *= ah; o[j][3] *= ah;
        }
        #pragma unroll
        for (int jj = 0; jj < 4; jj++) {
            unsigned pa[4] = { pl[2*jj], ph[2*jj], pl[2*jj+1], ph[2*jj+1] };
            #pragma unroll
            for (int j = 0; j < 8; j += 2) {
                unsigned b0, b1, b2, b3;
                unsigned addr = smem_u32(&Vs[(jj*16 + (lane & 15))*FLD + j*8 + (lane >> 4)*8]);
                ldsm_x4t(b0, b1, b2, b3, addr);
                mma16816(o[j],   pa, b0, b1);
                mma16816(o[j+1], pa, b2, b3);
            }
        }
    }

    // ---- epilogue: ctx[b, s, h*64+dk] = O / l ----
    float il = 1.f / l_lo, ih = 1.f / l_hi;
    int b = bh >> 4, h = bh & 15;
    __half* dlo = ctx + ((size_t)(b * S_ + qlo)) * D_ + h * DK_;
    __half* dhi = dlo + (size_t)8 * D_;
    #pragma unroll
    for (int j = 0; j < 8; j++) {
        int cidx = j*8 + 2*cc;
        *(__half2*)&dlo[cidx] = __floats2half2_rn(o[j][0]*il, o[j][1]*il);
        *(__half2*)&dhi[cidx] = __floats2half2_rn(o[j][2]*ih, o[j][3]*ih);
    }
}

// ---------------- launch ----------------
static void* symaddr(const void* sym) {
    void* p = nullptr;
    cudaGetSymbolAddress(&p, sym);
    return p;
}

extern "C" void kernel_launch(void* const* d_in, const int* in_sizes, int n_in,
                              void* d_out, int out_size)
{
    const float* q    = (const float*)d_in[0];
    const float* k    = (const float*)d_in[1];
    const float* v    = (const float*)d_in[2];
    const int*   mask = (const int*)  d_in[3];
    const float* w_q  = (const float*)d_in[4];
    const float* w_k  = (const float*)d_in[5];
    const float* w_v  = (const float*)d_in[6];
    const float* w_o  = (const float*)d_in[7];

    __half* qh = (__half*)symaddr(g_qh);
    __half* kh = (__half*)symaddr(g_kh);
    __half* vh = (__half*)symaddr(g_vh);
    __half* wq = (__half*)symaddr(g_wq);
    __half* wk = (__half*)symaddr(g_wk);
    __half* wv = (__half*)symaddr(g_wv);
    __half* wo = (__half*)symaddr(g_wo);
    __half* Qp = (__half*)symaddr(g_Q);
    __half* Kp = (__half*)symaddr(g_K);
    __half* Vp = (__half*)symaddr(g_V);
    __half* cx = (__half*)symaddr(g_ctx);
    unsigned* mb = (unsigned*)symaddr(g_maskbits);

    // converts
    int n4 = BS_ * D_ / 4;
    f2h_kernel<<<n4/256, 256>>>((const float4*)q, (__half2*)qh, n4);
    f2h_kernel<<<n4/256, 256>>>((const float4*)k, (__half2*)kh, n4);
    f2h_kernel<<<n4/256, 256>>>((const float4*)v, (__half2*)vh, n4);
    int w4 = D_ * D_ / 4;
    f2h_kernel<<<w4/256, 256>>>((const float4*)w_q, (__half2*)wq, w4);
    f2h_kernel<<<w4/256, 256>>>((const float4*)w_k, (__half2*)wk, w4);
    f2h_kernel<<<w4/256, 256>>>((const float4*)w_v, (__half2*)wv, w4);
    f2h_kernel<<<w4/256, 256>>>((const float4*)w_o, (__half2*)wo, w4);

    // mask bitpack
    maskpack_kernel<<<(S_*S_)/256, 256>>>(mask, mb, S_*S_);

    // projections -> head-major Q/K/V
    const int GEMM_SMEM = 40960;
    dim3 gg(D_/128, BS_/128);
    gemm_kernel<true><<<gg, 256, GEMM_SMEM>>>(qh, wq, Qp, nullptr);
    gemm_kernel<true><<<gg, 256, GEMM_SMEM>>>(kh, wk, Kp, nullptr);
    gemm_kernel<true><<<gg, 256, GEMM_SMEM>>>(vh, wv, Vp, nullptr);

    // flash attention (register-resident FA2)
    flash2_kernel<<<dim3(S_/FBM, B_*H_), 256>>>(Qp, Kp, Vp, mb, cx);

    // output projection (fp32 out)
    gemm_kernel<false><<<gg, 256, GEMM_SMEM>>>(cx, wo, nullptr, (float*)d_out);
}

// round 3
// speedup vs baseline: 1.8639x; 1.0574x over previous
#include <cuda_runtime.h>
#include <cuda_fp16.h>
#include <mma.h>

using namespace nvcuda;

#define B_  2
#define S_  4096
#define D_  1024
#define H_  16
#define DK_ 64
#define BS_ (B_*S_)          // 8192 rows

// ---------------- device scratch (static, no allocations) ----------------
__device__ __half g_qh[BS_*D_];
__device__ __half g_kh[BS_*D_];
__device__ __half g_vh[BS_*D_];
__device__ __half g_wq[D_*D_];
__device__ __half g_wk[D_*D_];
__device__ __half g_wv[D_*D_];
__device__ __half g_wo[D_*D_];
__device__ __half g_Q[BS_*D_];    // [B,H,S,DK]
__device__ __half g_K[BS_*D_];    // [B,H,S,DK]
__device__ __half g_V[BS_*D_];    // [B,H,S,DK]
__device__ __half g_ctx[BS_*D_];  // [B,S,D]
__device__ unsigned g_maskbits[S_*S_/32];

// ---------------- small PTX helpers ----------------
__device__ __forceinline__ unsigned smem_u32(const void* p) {
    return (unsigned)__cvta_generic_to_shared(p);
}
__device__ __forceinline__ void cp_async16(void* dst, const void* src) {
    asm volatile("cp.async.cg.shared.global [%0], [%1], 16;"
                 :: "r"(smem_u32(dst)), "l"(src));
}
#define CP_COMMIT() asm volatile("cp.async.commit_group;")
#define CP_WAIT0()  asm volatile("cp.async.wait_group 0;")

__device__ __forceinline__ void ldsm_x4(unsigned& r0, unsigned& r1, unsigned& r2, unsigned& r3,
                                        unsigned a) {
    asm volatile("ldmatrix.sync.aligned.m8n8.x4.shared.b16 {%0,%1,%2,%3},[%4];"
                 : "=r"(r0), "=r"(r1), "=r"(r2), "=r"(r3) : "r"(a));
}
__device__ __forceinline__ void ldsm_x4t(unsigned& r0, unsigned& r1, unsigned& r2, unsigned& r3,
                                         unsigned a) {
    asm volatile("ldmatrix.sync.aligned.m8n8.x4.trans.shared.b16 {%0,%1,%2,%3},[%4];"
                 : "=r"(r0), "=r"(r1), "=r"(r2), "=r"(r3) : "r"(a));
}
__device__ __forceinline__ void mma16816(float* c, const unsigned a[4], unsigned b0, unsigned b1) {
    asm volatile("mma.sync.aligned.m16n8k16.row.col.f32.f16.f16.f32 "
                 "{%0,%1,%2,%3},{%4,%5,%6,%7},{%8,%9},{%0,%1,%2,%3};"
                 : "+f"(c[0]), "+f"(c[1]), "+f"(c[2]), "+f"(c[3])
                 : "r"(a[0]), "r"(a[1]), "r"(a[2]), "r"(a[3]), "r"(b0), "r"(b1));
}
__device__ __forceinline__ unsigned packh2(float lo, float hi) {
    __half2 h = __floats2half2_rn(lo, hi);
    return *(unsigned*)&h;
}

// ---------------- fused fp32 -> fp16 convert (7 tensors, one launch) ----------------
__global__ void f2h_multi_kernel(
    const float4* __restrict__ s0, const float4* __restrict__ s1,
    const float4* __restrict__ s2, const float4* __restrict__ s3,
    const float4* __restrict__ s4, const float4* __restrict__ s5,
    const float4* __restrict__ s6,
    __half2* __restrict__ d0, __half2* __restrict__ d1,
    __half2* __restrict__ d2, __half2* __restrict__ d3,
    __half2* __restrict__ d4, __half2* __restrict__ d5,
    __half2* __restrict__ d6)
{
    int t = blockIdx.y;
    const float4* src; __half2* dst; int n4;
    switch (t) {
        case 0: src = s0; dst = d0; n4 = BS_*D_/4; break;
        case 1: src = s1; dst = d1; n4 = BS_*D_/4; break;
        case 2: src = s2; dst = d2; n4 = BS_*D_/4; break;
        case 3: src = s3; dst = d3; n4 = D_*D_/4; break;
        case 4: src = s4; dst = d4; n4 = D_*D_/4; break;
        case 5: src = s5; dst = d5; n4 = D_*D_/4; break;
        default: src = s6; dst = d6; n4 = D_*D_/4; break;
    }
    int i = blockIdx.x * blockDim.x + threadIdx.x;
    if (i < n4) {
        float4 v = src[i];
        dst[2*i + 0] = __floats2half2_rn(v.x, v.y);
        dst[2*i + 1] = __floats2half2_rn(v.z, v.w);
    }
}

// ---------------- mask -> bitmask ----------------
__global__ void maskpack_kernel(const int* __restrict__ mask, unsigned* __restrict__ out, int n) {
    int i = blockIdx.x * blockDim.x + threadIdx.x;
    unsigned b = __ballot_sync(0xffffffffu, (i < n) && (mask[i] != 0));
    if (((threadIdx.x & 31) == 0) && i < n) out[i >> 5] = b;
}

// ---------------- GEMM: C[M,1024] = A[M,1024] * W[1024,1024]^T ----------------
// 2-stage cp.async pipeline, 128x128 tile, k-step 32.
// HEAD_OUT: write half, scattered to [B,H,S,DK]. else: write fp32 [M,1024].
template <bool HEAD_OUT>
__global__ void __launch_bounds__(256) gemm_kernel(
    const __half* __restrict__ A,
    const __half* __restrict__ W,
    __half* __restrict__ outH,
    float* __restrict__ outF)
{
    extern __shared__ __half smem[];    // [As0|Bs0|As1|Bs1], each 128*40 halfs = 40960 B total

    int tid  = threadIdx.x;
    int wid  = tid >> 5;
    int lane = tid & 31;
    int bm = blockIdx.y * 128;
    int bn = blockIdx.x * 128;
    int warp_m = wid >> 1;   // 0..3 -> 32 rows each
    int warp_n = wid & 1;    // 0..1 -> 64 cols each

    wmma::fragment<wmma::accumulator, 16, 16, 16, float> acc[2][4];
    #pragma unroll
    for (int i = 0; i < 2; i++)
        #pragma unroll
        for (int j = 0; j < 4; j++)
            wmma::fill_fragment(acc[i][j], 0.0f);

    auto ldst = [&](int k0, int s) {
        __half* As = smem + s * 10240;
        __half* Bs = As + 5120;
        #pragma unroll
        for (int i = 0; i < 2; i++) {
            int c = tid + 256 * i;              // 0..511
            int r = c >> 2, coff = (c & 3) * 8;
            cp_async16(&As[r*40 + coff], &A[(size_t)(bm + r) * 1024 + k0 + coff]);
        }
        #pragma unroll
        for (int i = 0; i < 2; i++) {
            int c = tid + 256 * i;
            int r = c >> 2, coff = (c & 3) * 8;
            cp_async16(&Bs[r*40 + coff], &W[(size_t)(bn + r) * 1024 + k0 + coff]);
        }
    };

    ldst(0, 0); CP_COMMIT();

    for (int it = 0; it < 32; it++) {
        CP_WAIT0();
        __syncthreads();
        if (it < 31) ldst((it + 1) * 32, (it + 1) & 1);
        CP_COMMIT();

        const __half* As = smem + (it & 1) * 10240;
        const __half* Bs = As + 5120;
        #pragma unroll
        for (int kk = 0; kk < 2; kk++) {
            wmma::fragment<wmma::matrix_a, 16, 16, 16, __half, wmma::row_major> af[2];
            wmma::fragment<wmma::matrix_b, 16, 16, 16, __half, wmma::col_major> bf[4];
            #pragma unroll
            for (int i = 0; i < 2; i++)
                wmma::load_matrix_sync(af[i], &As[(warp_m*32 + i*16)*40 + kk*16], 40);
            #pragma unroll
            for (int j = 0; j < 4; j++)
                wmma::load_matrix_sync(bf[j], &Bs[(warp_n*64 + j*16)*40 + kk*16], 40);
            #pragma unroll
            for (int i = 0; i < 2; i++)
                #pragma unroll
                for (int j = 0; j < 4; j++)
                    wmma::mma_sync(acc[i][j], af[i], bf[j], acc[i][j]);
        }
    }
    __syncthreads();   // before aliasing smem as stage

    if (!HEAD_OUT) {
        #pragma unroll
        for (int i = 0; i < 2; i++)
            #pragma unroll
            for (int j = 0; j < 4; j++) {
                int m0 = bm + warp_m*32 + i*16;
                int n0 = bn + warp_n*64 + j*16;
                wmma::store_matrix_sync(outF + (size_t)m0 * 1024 + n0, acc[i][j], 1024,
                                        wmma::mem_row_major);
            }
    } else {
        float* mystage = (float*)smem + wid * 320;   // 16x20
        #pragma unroll
        for (int i = 0; i < 2; i++)
            #pragma unroll
            for (int j = 0; j < 4; j++) {
                wmma::store_matrix_sync(mystage, acc[i][j], 20, wmma::mem_row_major);
                __syncwarp();
                int m0 = bm + warp_m*32 + i*16;
                int e0 = bn + warp_n*64 + j*16;
                int h   = e0 >> 6;
                int dk0 = e0 & 63;
                int b   = m0 >> 12;
                int s0  = m0 & 4095;
                int r  = lane >> 1;
                int c0 = (lane & 1) * 8;
                const float* srow = &mystage[r * 20 + c0];
                __half* drow = outH + ((size_t)(b * H_ + h) * S_ + s0 + r) * DK_ + dk0 + c0;
                #pragma unroll
                for (int c = 0; c < 8; c++) drow[c] = __float2half_rn(srow[c]);
                __syncwarp();
            }
    }
}

// ---------------- Flash attention v2: register-resident, mma.sync ----------------
// grid (S/128, B*H), 256 threads (8 warps), each warp owns 16 q-rows.
// K/V tiles of 64 keys, 2-stage cp.async double buffer. S/P/O all in registers.
// __launch_bounds__(256, 2): cap at 128 regs -> 2 CTAs/SM -> 4 warps/SMSP for
// cross-warp overlap of HMMA / MUFU.EX2 / LDSM.
#define FBM 128
#define FBN 64
#define FLD 72                 // half stride (144 B) -> conflict-free ldmatrix
#define FSTG (64*FLD)          // halfs per K (or V) tile
#define SCALE_LOG2E 0.180336879f   // 0.125 * log2(e)

__global__ void __launch_bounds__(256, 2) flash2_kernel(
    const __half* __restrict__ Qp,
    const __half* __restrict__ Kp,
    const __half* __restrict__ Vp,
    const unsigned* __restrict__ maskbits,
    __half* __restrict__ ctx)
{
    __shared__ __half sm[2 * 2 * FSTG];   // [K0|V0|K1|V1] = 36864 B

    int tid  = threadIdx.x;
    int lane = tid & 31;
    int wid  = tid >> 5;
    int gr   = lane >> 2;      // row-in-16 group (rows gr and gr+8)
    int cc   = lane & 3;       // col pair selector

    int q0 = blockIdx.x * FBM;
    int bh = blockIdx.y;
    const __half* Qbase = Qp + ((size_t)bh * S_ + q0) * DK_;
    const __half* Kbase = Kp + (size_t)bh * S_ * DK_;
    const __half* Vbase = Vp + (size_t)bh * S_ * DK_;

    // ---- stage Q (128x64) through smem, ldmatrix into persistent A frags ----
    #pragma unroll
    for (int i = 0; i < 4; i++) {
        int c = tid + 256 * i;               // 0..1023
        int r = c >> 3, col = (c & 7) * 8;
        *(uint4*)&sm[r*FLD + col] = *(const uint4*)&Qbase[r*DK_ + col];
    }
    __syncthreads();

    unsigned qf[4][4];
    {
        int rbase = wid * 16;
        #pragma unroll
        for (int kk = 0; kk < 4; kk++) {
            unsigned addr = smem_u32(&sm[(rbase + (lane & 15))*FLD + (lane >> 4)*8 + kk*16]);
            ldsm_x4(qf[kk][0], qf[kk][1], qf[kk][2], qf[kk][3], addr);
        }
    }
    __syncthreads();

    // ---- per-thread softmax state ----
    float o[8][4];
    #pragma unroll
    for (int j = 0; j < 8; j++) { o[j][0]=0.f; o[j][1]=0.f; o[j][2]=0.f; o[j][3]=0.f; }
    float m_lo = -1e30f, m_hi = -1e30f, l_lo = 0.f, l_hi = 0.f;

    int qlo = q0 + wid*16 + gr;
    const unsigned* mrow_lo = maskbits + (size_t)qlo * (S_/32);
    const unsigned* mrow_hi = mrow_lo + 8 * (S_/32);

    auto load_kv = [&](int j0, int s) {
        __half* Ks = sm + s * 2 * FSTG;
        __half* Vs = Ks + FSTG;
        #pragma unroll
        for (int i = 0; i < 2; i++) {
            int c = tid + 256 * i;           // 0..511
            int r = c >> 3, col = (c & 7) * 8;
            cp_async16(&Ks[r*FLD + col], &Kbase[(size_t)(j0 + r)*DK_ + col]);
        }
        #pragma unroll
        for (int i = 0; i < 2; i++) {
            int c = tid + 256 * i;
            int r = c >> 3, col = (c & 7) * 8;
            cp_async16(&Vs[r*FLD + col], &Vbase[(size_t)(j0 + r)*DK_ + col]);
        }
    };

    load_kv(0, 0); CP_COMMIT();

    for (int it = 0; it < S_/FBN; it++) {
        int j0 = it * FBN;
        CP_WAIT0();
        __syncthreads();
        if (it + 1 < S_/FBN) load_kv(j0 + FBN, (it + 1) & 1);
        CP_COMMIT();

        const __half* Ks = sm + (it & 1) * 2 * FSTG;
        const __half* Vs = Ks + FSTG;

        // ---- S = Q K^T ----
        float sc[8][4];
        #pragma unroll
        for (int j = 0; j < 8; j++) { sc[j][0]=0.f; sc[j][1]=0.f; sc[j][2]=0.f; sc[j][3]=0.f; }
        #pragma unroll
        for (int j = 0; j < 8; j++) {
            #pragma unroll
            for (int kk = 0; kk < 4; kk += 2) {
                unsigned b0, b1, b2, b3;
                unsigned addr = smem_u32(&Ks[(j*8 + (lane & 7))*FLD + kk*16 + (lane >> 3)*8]);
                ldsm_x4(b0, b1, b2, b3, addr);
                mma16816(sc[j], qf[kk],   b0, b1);
                mma16816(sc[j], qf[kk+1], b2, b3);
            }
        }

        // ---- mask + scale + row max ----
        unsigned long long bm_lo = *(const unsigned long long*)(mrow_lo + (j0 >> 5));
        unsigned long long bm_hi = *(const unsigned long long*)(mrow_hi + (j0 >> 5));
        float mxl = -1e30f, mxh = -1e30f;
        #pragma unroll
        for (int j = 0; j < 8; j++) {
            int t0 = j*8 + 2*cc;
            float s0 = ((bm_lo >> t0)     & 1ull) ? sc[j][0]*SCALE_LOG2E : -6e8f;
            float s1 = ((bm_lo >> (t0+1)) & 1ull) ? sc[j][1]*SCALE_LOG2E : -6e8f;
            float s2 = ((bm_hi >> t0)     & 1ull) ? sc[j][2]*SCALE_LOG2E : -6e8f;
            float s3 = ((bm_hi >> (t0+1)) & 1ull) ? sc[j][3]*SCALE_LOG2E : -6e8f;
            sc[j][0]=s0; sc[j][1]=s1; sc[j][2]=s2; sc[j][3]=s3;
            mxl = fmaxf(mxl, fmaxf(s0, s1));
            mxh = fmaxf(mxh, fmaxf(s2, s3));
        }
        mxl = fmaxf(mxl, __shfl_xor_sync(0xffffffffu, mxl, 1));
        mxl = fmaxf(mxl, __shfl_xor_sync(0xffffffffu, mxl, 2));
        mxh = fmaxf(mxh, __shfl_xor_sync(0xffffffffu, mxh, 1));
        mxh = fmaxf(mxh, __shfl_xor_sync(0xffffffffu, mxh, 2));

        float mnl = fmaxf(m_lo, mxl), mnh = fmaxf(m_hi, mxh);
        float al = exp2f(m_lo - mnl), ah = exp2f(m_hi - mnh);
        m_lo = mnl; m_hi = mnh;

        // ---- p = 2^(s-m), pack to fp16 A-frags, accumulate l ----
        unsigned pl[8], ph[8];
        float sl = 0.f, sh = 0.f;
        #pragma unroll
        for (int j = 0; j < 8; j++) {
            float p0 = exp2f(sc[j][0] - mnl), p1 = exp2f(sc[j][1] - mnl);
            float p2 = exp2f(sc[j][2] - mnh), p3 = exp2f(sc[j][3] - mnh);
            sl += p0 + p1; sh += p2 + p3;
            pl[j] = packh2(p0, p1);
            ph[j] = packh2(p2, p3);
        }
        sl += __shfl_xor_sync(0xffffffffu, sl, 1);
        sl += __shfl_xor_sync(0xffffffffu, sl, 2);
        sh += __shfl_xor_sync(0xffffffffu, sh, 1);
        sh += __shfl_xor_sync(0xffffffffu, sh, 2);
        l_lo = l_lo * al + sl;
        l_hi = l_hi * ah + sh;

        // ---- rescale O, then O += P V ----
        #pragma unroll
        for (int j = 0; j < 8; j++) {
            o[j][0] *= al; o[j][1] *= al; o[j][2] *= ah; o[j][3] *= ah;
        }
        #pragma unroll
        for (int jj = 0; jj < 4; jj++) {
            unsigned pa[4] = { pl[2*jj], ph[2*jj], pl[2*jj+1], ph[2*jj+1] };
            #pragma unroll
            for (int j = 0; j < 8; j += 2) {
                unsigned b0, b1, b2, b3;
                unsigned addr = smem_u32(&Vs[(jj*16 + (lane & 15))*FLD + j*8 + (lane >> 4)*8]);
                ldsm_x4t(b0, b1, b2, b3, addr);
                mma16816(o[j],   pa, b0, b1);
                mma16816(o[j+1], pa, b2, b3);
            }
        }
    }

    // ---- epilogue: ctx[b, s, h*64+dk] = O / l ----
    float il = 1.f / l_lo, ih = 1.f / l_hi;
    int b = bh >> 4, h = bh & 15;
    __half* dlo = ctx + ((size_t)(b * S_ + qlo)) * D_ + h * DK_;
    __half* dhi = dlo + (size_t)8 * D_;
    #pragma unroll
    for (int j = 0; j < 8; j++) {
        int cidx = j*8 + 2*cc;
        *(__half2*)&dlo[cidx] = __floats2half2_rn(o[j][0]*il, o[j][1]*il);
        *(__half2*)&dhi[cidx] = __floats2half2_rn(o[j][2]*ih, o[j][3]*ih);
    }
}

// ---------------- launch ----------------
static void* symaddr(const void* sym) {
    void* p = nullptr;
    cudaGetSymbolAddress(&p, sym);
    return p;
}

extern "C" void kernel_launch(void* const* d_in, const int* in_sizes, int n_in,
                              void* d_out, int out_size)
{
    const float* q    = (const float*)d_in[0];
    const float* k    = (const float*)d_in[1];
    const float* v    = (const float*)d_in[2];
    const int*   mask = (const int*)  d_in[3];
    const float* w_q  = (const float*)d_in[4];
    const float* w_k  = (const float*)d_in[5];
    const float* w_v  = (const float*)d_in[6];
    const float* w_o  = (const float*)d_in[7];

    __half* qh = (__half*)symaddr(g_qh);
    __half* kh = (__half*)symaddr(g_kh);
    __half* vh = (__half*)symaddr(g_vh);
    __half* wq = (__half*)symaddr(g_wq);
    __half* wk = (__half*)symaddr(g_wk);
    __half* wv = (__half*)symaddr(g_wv);
    __half* wo = (__half*)symaddr(g_wo);
    __half* Qp = (__half*)symaddr(g_Q);
    __half* Kp = (__half*)symaddr(g_K);
    __half* Vp = (__half*)symaddr(g_V);
    __half* cx = (__half*)symaddr(g_ctx);
    unsigned* mb = (unsigned*)symaddr(g_maskbits);

    // fused converts (1 launch): q,k,v then the 4 weights
    {
        dim3 cg(BS_*D_/4/256, 7);
        f2h_multi_kernel<<<cg, 256>>>(
            (const float4*)q, (const float4*)k, (const float4*)v,
            (const float4*)w_q, (const float4*)w_k, (const float4*)w_v, (const float4*)w_o,
            (__half2*)qh, (__half2*)kh, (__half2*)vh,
            (__half2*)wq, (__half2*)wk, (__half2*)wv, (__half2*)wo);
    }

    // mask bitpack
    maskpack_kernel<<<(S_*S_)/256, 256>>>(mask, mb, S_*S_);

    // projections -> head-major Q/K/V
    const int GEMM_SMEM = 40960;
    dim3 gg(D_/128, BS_/128);
    gemm_kernel<true><<<gg, 256, GEMM_SMEM>>>(qh, wq, Qp, nullptr);
    gemm_kernel<true><<<gg, 256, GEMM_SMEM>>>(kh, wk, Kp, nullptr);
    gemm_kernel<true><<<gg, 256, GEMM_SMEM>>>(vh, wv, Vp, nullptr);

    // flash attention (register-resident FA2, 2 CTAs/SM)
    flash2_kernel<<<dim3(S_/FBM, B_*H_), 256>>>(Qp, Kp, Vp, mb, cx);

    // output projection (fp32 out)
    gemm_kernel<false><<<gg, 256, GEMM_SMEM>>>(cx, wo, nullptr, (float*)d_out);
}

// round 5
// speedup vs baseline: 2.1761x; 1.1675x over previous
#include <cuda_runtime.h>
#include <cuda_fp16.h>
#include <cstdint>

#define B_  2
#define S_  4096
#define D_  1024
#define H_  16
#define DK_ 64
#define BS_ (B_*S_)          // 8192 rows

// ---------------- device scratch (static, no allocations) ----------------
__device__ __half g_qh[BS_*D_];
__device__ __half g_kh[BS_*D_];
__device__ __half g_vh[BS_*D_];
__device__ __half g_wq[D_*D_];
__device__ __half g_wk[D_*D_];
__device__ __half g_wv[D_*D_];
__device__ __half g_wo[D_*D_];
__device__ __half g_Q[BS_*D_];    // [B,H,S,DK]
__device__ __half g_K[BS_*D_];    // [B,H,S,DK]
__device__ __half g_V[BS_*D_];    // [B,H,S,DK]
__device__ __half g_ctx[BS_*D_];  // [B,S,D]
__device__ unsigned g_maskbits[S_*S_/32];

// ---------------- small PTX helpers ----------------
__device__ __forceinline__ unsigned smem_u32(const void* p) {
    return (unsigned)__cvta_generic_to_shared(p);
}
__device__ __forceinline__ void cp_async16(void* dst, const void* src) {
    asm volatile("cp.async.cg.shared.global [%0], [%1], 16;"
                 :: "r"(smem_u32(dst)), "l"(src));
}
#define CP_COMMIT() asm volatile("cp.async.commit_group;")
#define CP_WAIT0()  asm volatile("cp.async.wait_group 0;")

__device__ __forceinline__ void ldsm_x4(unsigned& r0, unsigned& r1, unsigned& r2, unsigned& r3,
                                        unsigned a) {
    asm volatile("ldmatrix.sync.aligned.m8n8.x4.shared.b16 {%0,%1,%2,%3},[%4];"
                 : "=r"(r0), "=r"(r1), "=r"(r2), "=r"(r3) : "r"(a));
}
__device__ __forceinline__ void ldsm_x4t(unsigned& r0, unsigned& r1, unsigned& r2, unsigned& r3,
                                         unsigned a) {
    asm volatile("ldmatrix.sync.aligned.m8n8.x4.trans.shared.b16 {%0,%1,%2,%3},[%4];"
                 : "=r"(r0), "=r"(r1), "=r"(r2), "=r"(r3) : "r"(a));
}
__device__ __forceinline__ void mma16816(float* c, const unsigned a[4], unsigned b0, unsigned b1) {
    asm volatile("mma.sync.aligned.m16n8k16.row.col.f32.f16.f16.f32 "
                 "{%0,%1,%2,%3},{%4,%5,%6,%7},{%8,%9},{%0,%1,%2,%3};"
                 : "+f"(c[0]), "+f"(c[1]), "+f"(c[2]), "+f"(c[3])
                 : "r"(a[0]), "r"(a[1]), "r"(a[2]), "r"(a[3]), "r"(b0), "r"(b1));
}
__device__ __forceinline__ unsigned packh2(float lo, float hi) {
    __half2 h = __floats2half2_rn(lo, hi);
    return *(unsigned*)&h;
}

// ---------------- fused fp32 -> fp16 convert (7 tensors, one launch) ----------------
__global__ void f2h_multi_kernel(
    const float4* __restrict__ s0, const float4* __restrict__ s1,
    const float4* __restrict__ s2, const float4* __restrict__ s3,
    const float4* __restrict__ s4, const float4* __restrict__ s5,
    const float4* __restrict__ s6,
    __half2* __restrict__ d0, __half2* __restrict__ d1,
    __half2* __restrict__ d2, __half2* __restrict__ d3,
    __half2* __restrict__ d4, __half2* __restrict__ d5,
    __half2* __restrict__ d6)
{
    int t = blockIdx.y;
    const float4* src; __half2* dst; int n4;
    switch (t) {
        case 0: src = s0; dst = d0; n4 = BS_*D_/4; break;
        case 1: src = s1; dst = d1; n4 = BS_*D_/4; break;
        case 2: src = s2; dst = d2; n4 = BS_*D_/4; break;
        case 3: src = s3; dst = d3; n4 = D_*D_/4; break;
        case 4: src = s4; dst = d4; n4 = D_*D_/4; break;
        case 5: src = s5; dst = d5; n4 = D_*D_/4; break;
        default: src = s6; dst = d6; n4 = D_*D_/4; break;
    }
    int i = blockIdx.x * blockDim.x + threadIdx.x;
    if (i < n4) {
        float4 v = src[i];
        dst[2*i + 0] = __floats2half2_rn(v.x, v.y);
        dst[2*i + 1] = __floats2half2_rn(v.z, v.w);
    }
}

// ---------------- mask -> bitmask ----------------
__global__ void maskpack_kernel(const int* __restrict__ mask, unsigned* __restrict__ out, int n) {
    int i = blockIdx.x * blockDim.x + threadIdx.x;
    unsigned b = __ballot_sync(0xffffffffu, (i < n) && (mask[i] != 0));
    if (((threadIdx.x & 31) == 0) && i < n) out[i >> 5] = b;
}

// ---------------- GEMM v2: raw mma.sync, C[M,1024] = A[M,1024] * W[1024,1024]^T --------
// 256 thr, 128x128 tile, warp tile 32x64, k-chunk 64, 2-stage cp.async.
// A and W both row-major with K contiguous (W row = output feature).
// Device core shared by the fused-projection kernel and the final projection.
#define G2_LD   72                      // half stride (144 B)
#define G2_TILE (128*G2_LD)             // halfs per A (or B) tile
#define G2_SMEM (2*2*G2_TILE*2)         // bytes: 2 stages x (A+B) = 73728

template <bool HEAD_OUT>
__device__ __forceinline__ void gemm2_core(
    const __half* __restrict__ A,
    const __half* __restrict__ W,
    __half* __restrict__ outH,
    float* __restrict__ outF,
    __half* gsm, int bm, int bn)
{
    int tid  = threadIdx.x;
    int lane = tid & 31;
    int wid  = tid >> 5;
    int warp_m = wid >> 1;       // 0..3 -> 32 rows
    int warp_n = wid & 1;        // 0..1 -> 64 cols
    int gr = lane >> 2;          // 0..7
    int cc = lane & 3;

    float c[2][8][4];
    #pragma unroll
    for (int i = 0; i < 2; i++)
        #pragma unroll
        for (int j = 0; j < 8; j++)
            { c[i][j][0]=0.f; c[i][j][1]=0.f; c[i][j][2]=0.f; c[i][j][3]=0.f; }

    auto load_stage = [&](int chunk, int s) {
        __half* As = gsm + s * 2 * G2_TILE;
        __half* Bs = As + G2_TILE;
        int k0 = chunk * 64;
        #pragma unroll
        for (int i = 0; i < 4; i++) {
            int idx = tid + 256 * i;             // 0..1023
            int r = idx >> 3, col = (idx & 7) * 8;
            cp_async16(&As[r*G2_LD + col], &A[(size_t)(bm + r) * 1024 + k0 + col]);
        }
        #pragma unroll
        for (int i = 0; i < 4; i++) {
            int idx = tid + 256 * i;
            int r = idx >> 3, col = (idx & 7) * 8;
            cp_async16(&Bs[r*G2_LD + col], &W[(size_t)(bn + r) * 1024 + k0 + col]);
        }
        CP_COMMIT();
    };

    load_stage(0, 0);

    for (int it = 0; it < 16; it++) {
        CP_WAIT0();
        __syncthreads();
        if (it < 15) load_stage(it + 1, (it + 1) & 1);

        const __half* As = gsm + (it & 1) * 2 * G2_TILE;
        const __half* Bs = As + G2_TILE;

        #pragma unroll
        for (int kk = 0; kk < 4; kk += 2) {
            // A frags for k16 steps kk and kk+1, both 16-row tiles
            unsigned a[2][2][4];
            #pragma unroll
            for (int t = 0; t < 2; t++)
                #pragma unroll
                for (int i = 0; i < 2; i++) {
                    unsigned addr = smem_u32(
                        &As[(warp_m*32 + i*16 + (lane & 15))*G2_LD + (kk + t)*16 + (lane >> 4)*8]);
                    ldsm_x4(a[t][i][0], a[t][i][1], a[t][i][2], a[t][i][3], addr);
                }
            #pragma unroll
            for (int j = 0; j < 8; j++) {
                unsigned b0, b1, b2, b3;
                unsigned addr = smem_u32(
                    &Bs[(warp_n*64 + j*8 + (lane & 7))*G2_LD + kk*16 + (lane >> 3)*8]);
                ldsm_x4(b0, b1, b2, b3, addr);
                mma16816(c[0][j], a[0][0], b0, b1);
                mma16816(c[1][j], a[0][1], b0, b1);
                mma16816(c[0][j], a[1][0], b2, b3);
                mma16816(c[1][j], a[1][1], b2, b3);
            }
        }
        __syncthreads();
    }

    // ---- epilogue: direct global writes from accumulators ----
    if (HEAD_OUT) {
        int e0 = bn + warp_n * 64;              // 64-aligned -> single head per warp
        int h = e0 >> 6;
        #pragma unroll
        for (int i = 0; i < 2; i++) {
            int m0 = bm + warp_m*32 + i*16 + gr;
            int b = m0 >> 12, s0 = m0 & 4095;
            __half* dst0 = outH + ((size_t)(b*H_ + h) * S_ + s0) * DK_;
            __half* dst1 = dst0 + (size_t)8 * DK_;
            #pragma unroll
            for (int j = 0; j < 8; j++) {
                int col = j*8 + 2*cc;
                *(__half2*)&dst0[col] = __floats2half2_rn(c[i][j][0], c[i][j][1]);
                *(__half2*)&dst1[col] = __floats2half2_rn(c[i][j][2], c[i][j][3]);
            }
        }
    } else {
        int e0 = bn + warp_n * 64;
        #pragma unroll
        for (int i = 0; i < 2; i++) {
            int m0 = bm + warp_m*32 + i*16 + gr;
            float* dst0 = outF + (size_t)m0 * 1024 + e0;
            float* dst1 = dst0 + (size_t)8 * 1024;
            #pragma unroll
            for (int j = 0; j < 8; j++) {
                int col = j*8 + 2*cc;
                *(float2*)&dst0[col] = make_float2(c[i][j][0], c[i][j][1]);
                *(float2*)&dst1[col] = make_float2(c[i][j][2], c[i][j][3]);
            }
        }
    }
}

// fused Q/K/V projections: blockIdx.z selects (input, weight, output)
__global__ void __launch_bounds__(256, 2) gemm_qkv_kernel(
    const __half* __restrict__ a0, const __half* __restrict__ a1, const __half* __restrict__ a2,
    const __half* __restrict__ w0, const __half* __restrict__ w1, const __half* __restrict__ w2,
    __half* __restrict__ o0, __half* __restrict__ o1, __half* __restrict__ o2)
{
    extern __shared__ __half gsm[];
    const __half* A; const __half* W; __half* O;
    if (blockIdx.z == 0)      { A = a0; W = w0; O = o0; }
    else if (blockIdx.z == 1) { A = a1; W = w1; O = o1; }
    else                      { A = a2; W = w2; O = o2; }
    gemm2_core<true>(A, W, O, nullptr, gsm, blockIdx.y * 128, blockIdx.x * 128);
}

// final output projection (fp32 out)
__global__ void __launch_bounds__(256, 2) gemm_out_kernel(
    const __half* __restrict__ A, const __half* __restrict__ W, float* __restrict__ outF)
{
    extern __shared__ __half gsm[];
    gemm2_core<false>(A, W, nullptr, outF, gsm, blockIdx.y * 128, blockIdx.x * 128);
}

// ---------------- Flash attention v2: register-resident, mma.sync ----------------
#define FBM 128
#define FBN 64
#define FLD 72                 // half stride (144 B) -> conflict-free ldmatrix
#define FSTG (64*FLD)          // halfs per K (or V) tile
#define SCALE_LOG2E 0.180336879f   // 0.125 * log2(e)

__global__ void __launch_bounds__(256, 2) flash2_kernel(
    const __half* __restrict__ Qp,
    const __half* __restrict__ Kp,
    const __half* __restrict__ Vp,
    const unsigned* __restrict__ maskbits,
    __half* __restrict__ ctx)
{
    __shared__ __half sm[2 * 2 * FSTG];   // [K0|V0|K1|V1] = 36864 B

    int tid  = threadIdx.x;
    int lane = tid & 31;
    int wid  = tid >> 5;
    int gr   = lane >> 2;      // row-in-16 group (rows gr and gr+8)
    int cc   = lane & 3;       // col pair selector

    int q0 = blockIdx.x * FBM;
    int bh = blockIdx.y;
    const __half* Qbase = Qp + ((size_t)bh * S_ + q0) * DK_;
    const __half* Kbase = Kp + (size_t)bh * S_ * DK_;
    const __half* Vbase = Vp + (size_t)bh * S_ * DK_;

    // ---- stage Q (128x64) through smem, ldmatrix into persistent A frags ----
    #pragma unroll
    for (int i = 0; i < 4; i++) {
        int c = tid + 256 * i;               // 0..1023
        int r = c >> 3, col = (c & 7) * 8;
        *(uint4*)&sm[r*FLD + col] = *(const uint4*)&Qbase[r*DK_ + col];
    }
    __syncthreads();

    unsigned qf[4][4];
    {
        int rbase = wid * 16;
        #pragma unroll
        for (int kk = 0; kk < 4; kk++) {
            unsigned addr = smem_u32(&sm[(rbase + (lane & 15))*FLD + (lane >> 4)*8 + kk*16]);
            ldsm_x4(qf[kk][0], qf[kk][1], qf[kk][2], qf[kk][3], addr);
        }
    }
    __syncthreads();

    // ---- per-thread softmax state ----
    float o[8][4];
    #pragma unroll
    for (int j = 0; j < 8; j++) { o[j][0]=0.f; o[j][1]=0.f; o[j][2]=0.f; o[j][3]=0.f; }
    float m_lo = -1e30f, m_hi = -1e30f, l_lo = 0.f, l_hi = 0.f;

    int qlo = q0 + wid*16 + gr;
    const unsigned* mrow_lo = maskbits + (size_t)qlo * (S_/32);
    const unsigned* mrow_hi = mrow_lo + 8 * (S_/32);

    auto load_kv = [&](int j0, int s) {
        __half* Ks = sm + s * 2 * FSTG;
        __half* Vs = Ks + FSTG;
        #pragma unroll
        for (int i = 0; i < 2; i++) {
            int c = tid + 256 * i;           // 0..511
            int r = c >> 3, col = (c & 7) * 8;
            cp_async16(&Ks[r*FLD + col], &Kbase[(size_t)(j0 + r)*DK_ + col]);
        }
        #pragma unroll
        for (int i = 0; i < 2; i++) {
            int c = tid + 256 * i;
            int r = c >> 3, col = (c & 7) * 8;
            cp_async16(&Vs[r*FLD + col], &Vbase[(size_t)(j0 + r)*DK_ + col]);
        }
    };

    load_kv(0, 0); CP_COMMIT();

    for (int it = 0; it < S_/FBN; it++) {
        int j0 = it * FBN;
        CP_WAIT0();
        __syncthreads();
        if (it + 1 < S_/FBN) load_kv(j0 + FBN, (it + 1) & 1);
        CP_COMMIT();

        const __half* Ks = sm + (it & 1) * 2 * FSTG;
        const __half* Vs = Ks + FSTG;

        // ---- S = Q K^T ----
        float sc[8][4];
        #pragma unroll
        for (int j = 0; j < 8; j++) { sc[j][0]=0.f; sc[j][1]=0.f; sc[j][2]=0.f; sc[j][3]=0.f; }
        #pragma unroll
        for (int j = 0; j < 8; j++) {
            #pragma unroll
            for (int kk = 0; kk < 4; kk += 2) {
                unsigned b0, b1, b2, b3;
                unsigned addr = smem_u32(&Ks[(j*8 + (lane & 7))*FLD + kk*16 + (lane >> 3)*8]);
                ldsm_x4(b0, b1, b2, b3, addr);
                mma16816(sc[j], qf[kk],   b0, b1);
                mma16816(sc[j], qf[kk+1], b2, b3);
            }
        }

        // ---- mask + scale + row max ----
        unsigned long long bm_lo = *(const unsigned long long*)(mrow_lo + (j0 >> 5));
        unsigned long long bm_hi = *(const unsigned long long*)(mrow_hi + (j0 >> 5));
        float mxl = -1e30f, mxh = -1e30f;
        #pragma unroll
        for (int j = 0; j < 8; j++) {
            int t0 = j*8 + 2*cc;
            float s0 = ((bm_lo >> t0)     & 1ull) ? sc[j][0]*SCALE_LOG2E : -6e8f;
            float s1 = ((bm_lo >> (t0+1)) & 1ull) ? sc[j][1]*SCALE_LOG2E : -6e8f;
            float s2 = ((bm_hi >> t0)     & 1ull) ? sc[j][2]*SCALE_LOG2E : -6e8f;
            float s3 = ((bm_hi >> (t0+1)) & 1ull) ? sc[j][3]*SCALE_LOG2E : -6e8f;
            sc[j][0]=s0; sc[j][1]=s1; sc[j][2]=s2; sc[j][3]=s3;
            mxl = fmaxf(mxl, fmaxf(s0, s1));
            mxh = fmaxf(mxh, fmaxf(s2, s3));
        }
        mxl = fmaxf(mxl, __shfl_xor_sync(0xffffffffu, mxl, 1));
        mxl = fmaxf(mxl, __shfl_xor_sync(0xffffffffu, mxl, 2));
        mxh = fmaxf(mxh, __shfl_xor_sync(0xffffffffu, mxh, 1));
        mxh = fmaxf(mxh, __shfl_xor_sync(0xffffffffu, mxh, 2));

        float mnl = fmaxf(m_lo, mxl), mnh = fmaxf(m_hi, mxh);
        float al = exp2f(m_lo - mnl), ah = exp2f(m_hi - mnh);
        m_lo = mnl; m_hi = mnh;

        // ---- p = 2^(s-m), pack to fp16 A-frags, accumulate l ----
        unsigned pl[8], ph[8];
        float sl = 0.f, sh = 0.f;
        #pragma unroll
        for (int j = 0; j < 8; j++) {
            float p0 = exp2f(sc[j][0] - mnl), p1 = exp2f(sc[j][1] - mnl);
            float p2 = exp2f(sc[j][2] - mnh), p3 = exp2f(sc[j][3] - mnh);
            sl += p0 + p1; sh += p2 + p3;
            pl[j] = packh2(p0, p1);
            ph[j] = packh2(p2, p3);
        }
        sl += __shfl_xor_sync(0xffffffffu, sl, 1);
        sl += __shfl_xor_sync(0xffffffffu, sl, 2);
        sh += __shfl_xor_sync(0xffffffffu, sh, 1);
        sh += __shfl_xor_sync(0xffffffffu, sh, 2);
        l_lo = l_lo * al + sl;
        l_hi = l_hi * ah + sh;

        // ---- rescale O, then O += P V ----
        #pragma unroll
        for (int j = 0; j < 8; j++) {
            o[j][0] *= al; o[j][1] *= al; o[j][2] *= ah; o[j][3] *= ah;
        }
        #pragma unroll
        for (int jj = 0; jj < 4; jj++) {
            unsigned pa[4] = { pl[2*jj], ph[2*jj], pl[2*jj+1], ph[2*jj+1] };
            #pragma unroll
            for (int j = 0; j < 8; j += 2) {
                unsigned b0, b1, b2, b3;
                unsigned addr = smem_u32(&Vs[(jj*16 + (lane & 15))*FLD + j*8 + (lane >> 4)*8]);
                ldsm_x4t(b0, b1, b2, b3, addr);
                mma16816(o[j],   pa, b0, b1);
                mma16816(o[j+1], pa, b2, b3);
            }
        }
    }

    // ---- epilogue: ctx[b, s, h*64+dk] = O / l ----
    float il = 1.f / l_lo, ih = 1.f / l_hi;
    int b = bh >> 4, h = bh & 15;
    __half* dlo = ctx + ((size_t)(b * S_ + qlo)) * D_ + h * DK_;
    __half* dhi = dlo + (size_t)8 * D_;
    #pragma unroll
    for (int j = 0; j < 8; j++) {
        int cidx = j*8 + 2*cc;
        *(__half2*)&dlo[cidx] = __floats2half2_rn(o[j][0]*il, o[j][1]*il);
        *(__half2*)&dhi[cidx] = __floats2half2_rn(o[j][2]*ih, o[j][3]*ih);
    }
}

// ---------------- launch ----------------
static void* symaddr(const void* sym) {
    void* p = nullptr;
    cudaGetSymbolAddress(&p, sym);
    return p;
}

extern "C" void kernel_launch(void* const* d_in, const int* in_sizes, int n_in,
                              void* d_out, int out_size)
{
    const float* q    = (const float*)d_in[0];
    const float* k    = (const float*)d_in[1];
    const float* v    = (const float*)d_in[2];
    const int*   mask = (const int*)  d_in[3];
    const float* w_q  = (const float*)d_in[4];
    const float* w_k  = (const float*)d_in[5];
    const float* w_v  = (const float*)d_in[6];
    const float* w_o  = (const float*)d_in[7];

    __half* qh = (__half*)symaddr(g_qh);
    __half* kh = (__half*)symaddr(g_kh);
    __half* vh = (__half*)symaddr(g_vh);
    __half* wq = (__half*)symaddr(g_wq);
    __half* wk = (__half*)symaddr(g_wk);
    __half* wv = (__half*)symaddr(g_wv);
    __half* wo = (__half*)symaddr(g_wo);
    __half* Qp = (__half*)symaddr(g_Q);
    __half* Kp = (__half*)symaddr(g_K);
    __half* Vp = (__half*)symaddr(g_V);
    __half* cx = (__half*)symaddr(g_ctx);
    unsigned* mb = (unsigned*)symaddr(g_maskbits);

    // fused converts (1 launch): q,k,v then the 4 weights
    {
        dim3 cg(BS_*D_/4/256, 7);
        f2h_multi_kernel<<<cg, 256>>>(
            (const float4*)q, (const float4*)k, (const float4*)v,
            (const float4*)w_q, (const float4*)w_k, (const float4*)w_v, (const float4*)w_o,
            (__half2*)qh, (__half2*)kh, (__half2*)vh,
            (__half2*)wq, (__half2*)wk, (__half2*)wv, (__half2*)wo);
    }

    // mask bitpack
    maskpack_kernel<<<(S_*S_)/256, 256>>>(mask, mb, S_*S_);

    // projections -> head-major Q/K/V (fused single launch)
    cudaFuncSetAttribute(gemm_qkv_kernel, cudaFuncAttributeMaxDynamicSharedMemorySize, G2_SMEM);
    cudaFuncSetAttribute(gemm_out_kernel, cudaFuncAttributeMaxDynamicSharedMemorySize, G2_SMEM);
    dim3 gq(D_/128, BS_/128, 3);
    gemm_qkv_kernel<<<gq, 256, G2_SMEM>>>(qh, kh, vh, wq, wk, wv, Qp, Kp, Vp);

    // flash attention (register-resident FA2, 2 CTAs/SM)
    flash2_kernel<<<dim3(S_/FBM, B_*H_), 256>>>(Qp, Kp, Vp, mb, cx);

    // output projection (fp32 out)
    dim3 gg(D_/128, BS_/128);
    gemm_out_kernel<<<gg, 256, G2_SMEM>>>(cx, wo, (float*)d_out);
}

// round 6
// speedup vs baseline: 2.2744x; 1.0452x over previous
#include <cuda_runtime.h>
#include <cuda_fp16.h>
#include <cstdint>

#define B_  2
#define S_  4096
#define D_  1024
#define H_  16
#define DK_ 64
#define BS_ (B_*S_)          // 8192 rows

// ---------------- device scratch (static, no allocations) ----------------
__device__ __half g_qh[BS_*D_];
__device__ __half g_kh[BS_*D_];
__device__ __half g_vh[BS_*D_];
__device__ __half g_wq[D_*D_];
__device__ __half g_wk[D_*D_];
__device__ __half g_wv[D_*D_];
__device__ __half g_wo[D_*D_];
__device__ __half g_Q[BS_*D_];    // [B,H,S,DK]
__device__ __half g_K[BS_*D_];    // [B,H,S,DK]
__device__ __half g_V[BS_*D_];    // [B,H,S,DK]
__device__ __half g_ctx[BS_*D_];  // [B,S,D]
__device__ unsigned g_maskbits[S_*S_/32];

// ---------------- small PTX helpers ----------------
__device__ __forceinline__ unsigned smem_u32(const void* p) {
    return (unsigned)__cvta_generic_to_shared(p);
}
__device__ __forceinline__ void cp_async16(void* dst, const void* src) {
    asm volatile("cp.async.cg.shared.global [%0], [%1], 16;"
                 :: "r"(smem_u32(dst)), "l"(src));
}
#define CP_COMMIT() asm volatile("cp.async.commit_group;")
#define CP_WAIT0()  asm volatile("cp.async.wait_group 0;")

__device__ __forceinline__ void ldsm_x4(unsigned& r0, unsigned& r1, unsigned& r2, unsigned& r3,
                                        unsigned a) {
    asm volatile("ldmatrix.sync.aligned.m8n8.x4.shared.b16 {%0,%1,%2,%3},[%4];"
                 : "=r"(r0), "=r"(r1), "=r"(r2), "=r"(r3) : "r"(a));
}
__device__ __forceinline__ void ldsm_x4t(unsigned& r0, unsigned& r1, unsigned& r2, unsigned& r3,
                                         unsigned a) {
    asm volatile("ldmatrix.sync.aligned.m8n8.x4.trans.shared.b16 {%0,%1,%2,%3},[%4];"
                 : "=r"(r0), "=r"(r1), "=r"(r2), "=r"(r3) : "r"(a));
}
__device__ __forceinline__ void mma16816(float* c, const unsigned a[4], unsigned b0, unsigned b1) {
    asm volatile("mma.sync.aligned.m16n8k16.row.col.f32.f16.f16.f32 "
                 "{%0,%1,%2,%3},{%4,%5,%6,%7},{%8,%9},{%0,%1,%2,%3};"
                 : "+f"(c[0]), "+f"(c[1]), "+f"(c[2]), "+f"(c[3])
                 : "r"(a[0]), "r"(a[1]), "r"(a[2]), "r"(a[3]), "r"(b0), "r"(b1));
}
__device__ __forceinline__ unsigned packh2(float lo, float hi) {
    __half2 h = __floats2half2_rn(lo, hi);
    return *(unsigned*)&h;
}

// ---------------- fused fp32 -> fp16 convert (7 tensors, one launch) ----------------
__global__ void f2h_multi_kernel(
    const float4* __restrict__ s0, const float4* __restrict__ s1,
    const float4* __restrict__ s2, const float4* __restrict__ s3,
    const float4* __restrict__ s4, const float4* __restrict__ s5,
    const float4* __restrict__ s6,
    __half2* __restrict__ d0, __half2* __restrict__ d1,
    __half2* __restrict__ d2, __half2* __restrict__ d3,
    __half2* __restrict__ d4, __half2* __restrict__ d5,
    __half2* __restrict__ d6)
{
    int t = blockIdx.y;
    const float4* src; __half2* dst; int n4;
    switch (t) {
        case 0: src = s0; dst = d0; n4 = BS_*D_/4; break;
        case 1: src = s1; dst = d1; n4 = BS_*D_/4; break;
        case 2: src = s2; dst = d2; n4 = BS_*D_/4; break;
        case 3: src = s3; dst = d3; n4 = D_*D_/4; break;
        case 4: src = s4; dst = d4; n4 = D_*D_/4; break;
        case 5: src = s5; dst = d5; n4 = D_*D_/4; break;
        default: src = s6; dst = d6; n4 = D_*D_/4; break;
    }
    int i = blockIdx.x * blockDim.x + threadIdx.x;
    if (i < n4) {
        float4 v = src[i];
        dst[2*i + 0] = __floats2half2_rn(v.x, v.y);
        dst[2*i + 1] = __floats2half2_rn(v.z, v.w);
    }
}

// ---------------- mask -> bitmask ----------------
__global__ void maskpack_kernel(const int* __restrict__ mask, unsigned* __restrict__ out, int n) {
    int i = blockIdx.x * blockDim.x + threadIdx.x;
    unsigned b = __ballot_sync(0xffffffffu, (i < n) && (mask[i] != 0));
    if (((threadIdx.x & 31) == 0) && i < n) out[i >> 5] = b;
}

// ---------------- GEMM v2: raw mma.sync, C[M,1024] = A[M,1024] * W[1024,1024]^T --------
#define G2_LD   72                      // half stride (144 B)
#define G2_TILE (128*G2_LD)             // halfs per A (or B) tile
#define G2_SMEM (2*2*G2_TILE*2)         // bytes: 2 stages x (A+B) = 73728

template <bool HEAD_OUT>
__device__ __forceinline__ void gemm2_core(
    const __half* __restrict__ A,
    const __half* __restrict__ W,
    __half* __restrict__ outH,
    float* __restrict__ outF,
    __half* gsm, int bm, int bn)
{
    int tid  = threadIdx.x;
    int lane = tid & 31;
    int wid  = tid >> 5;
    int warp_m = wid >> 1;       // 0..3 -> 32 rows
    int warp_n = wid & 1;        // 0..1 -> 64 cols
    int gr = lane >> 2;          // 0..7
    int cc = lane & 3;

    float c[2][8][4];
    #pragma unroll
    for (int i = 0; i < 2; i++)
        #pragma unroll
        for (int j = 0; j < 8; j++)
            { c[i][j][0]=0.f; c[i][j][1]=0.f; c[i][j][2]=0.f; c[i][j][3]=0.f; }

    auto load_stage = [&](int chunk, int s) {
        __half* As = gsm + s * 2 * G2_TILE;
        __half* Bs = As + G2_TILE;
        int k0 = chunk * 64;
        #pragma unroll
        for (int i = 0; i < 4; i++) {
            int idx = tid + 256 * i;             // 0..1023
            int r = idx >> 3, col = (idx & 7) * 8;
            cp_async16(&As[r*G2_LD + col], &A[(size_t)(bm + r) * 1024 + k0 + col]);
        }
        #pragma unroll
        for (int i = 0; i < 4; i++) {
            int idx = tid + 256 * i;
            int r = idx >> 3, col = (idx & 7) * 8;
            cp_async16(&Bs[r*G2_LD + col], &W[(size_t)(bn + r) * 1024 + k0 + col]);
        }
        CP_COMMIT();
    };

    load_stage(0, 0);

    for (int it = 0; it < 16; it++) {
        CP_WAIT0();
        __syncthreads();
        if (it < 15) load_stage(it + 1, (it + 1) & 1);

        const __half* As = gsm + (it & 1) * 2 * G2_TILE;
        const __half* Bs = As + G2_TILE;

        #pragma unroll
        for (int kk = 0; kk < 4; kk += 2) {
            unsigned a[2][2][4];
            #pragma unroll
            for (int t = 0; t < 2; t++)
                #pragma unroll
                for (int i = 0; i < 2; i++) {
                    unsigned addr = smem_u32(
                        &As[(warp_m*32 + i*16 + (lane & 15))*G2_LD + (kk + t)*16 + (lane >> 4)*8]);
                    ldsm_x4(a[t][i][0], a[t][i][1], a[t][i][2], a[t][i][3], addr);
                }
            #pragma unroll
            for (int j = 0; j < 8; j++) {
                unsigned b0, b1, b2, b3;
                unsigned addr = smem_u32(
                    &Bs[(warp_n*64 + j*8 + (lane & 7))*G2_LD + kk*16 + (lane >> 3)*8]);
                ldsm_x4(b0, b1, b2, b3, addr);
                mma16816(c[0][j], a[0][0], b0, b1);
                mma16816(c[1][j], a[0][1], b0, b1);
                mma16816(c[0][j], a[1][0], b2, b3);
                mma16816(c[1][j], a[1][1], b2, b3);
            }
        }
        __syncthreads();
    }

    // ---- epilogue: direct global writes from accumulators ----
    if (HEAD_OUT) {
        int e0 = bn + warp_n * 64;              // 64-aligned -> single head per warp
        int h = e0 >> 6;
        #pragma unroll
        for (int i = 0; i < 2; i++) {
            int m0 = bm + warp_m*32 + i*16 + gr;
            int b = m0 >> 12, s0 = m0 & 4095;
            __half* dst0 = outH + ((size_t)(b*H_ + h) * S_ + s0) * DK_;
            __half* dst1 = dst0 + (size_t)8 * DK_;
            #pragma unroll
            for (int j = 0; j < 8; j++) {
                int col = j*8 + 2*cc;
                *(__half2*)&dst0[col] = __floats2half2_rn(c[i][j][0], c[i][j][1]);
                *(__half2*)&dst1[col] = __floats2half2_rn(c[i][j][2], c[i][j][3]);
            }
        }
    } else {
        int e0 = bn + warp_n * 64;
        #pragma unroll
        for (int i = 0; i < 2; i++) {
            int m0 = bm + warp_m*32 + i*16 + gr;
            float* dst0 = outF + (size_t)m0 * 1024 + e0;
            float* dst1 = dst0 + (size_t)8 * 1024;
            #pragma unroll
            for (int j = 0; j < 8; j++) {
                int col = j*8 + 2*cc;
                *(float2*)&dst0[col] = make_float2(c[i][j][0], c[i][j][1]);
                *(float2*)&dst1[col] = make_float2(c[i][j][2], c[i][j][3]);
            }
        }
    }
}

__global__ void __launch_bounds__(256, 2) gemm_qkv_kernel(
    const __half* __restrict__ a0, const __half* __restrict__ a1, const __half* __restrict__ a2,
    const __half* __restrict__ w0, const __half* __restrict__ w1, const __half* __restrict__ w2,
    __half* __restrict__ o0, __half* __restrict__ o1, __half* __restrict__ o2)
{
    extern __shared__ __half gsm[];
    const __half* A; const __half* W; __half* O;
    if (blockIdx.z == 0)      { A = a0; W = w0; O = o0; }
    else if (blockIdx.z == 1) { A = a1; W = w1; O = o1; }
    else                      { A = a2; W = w2; O = o2; }
    gemm2_core<true>(A, W, O, nullptr, gsm, blockIdx.y * 128, blockIdx.x * 128);
}

__global__ void __launch_bounds__(256, 2) gemm_out_kernel(
    const __half* __restrict__ A, const __half* __restrict__ W, float* __restrict__ outF)
{
    extern __shared__ __half gsm[];
    gemm2_core<false>(A, W, nullptr, outF, gsm, blockIdx.y * 128, blockIdx.x * 128);
}

// ---------------- Flash attention v3: 32 q-rows/warp, 128 threads ----------------
// grid (S/128, B*H), 4 warps, each warp owns 32 q-rows (two 16-row mma tiles
// sharing every K/V B-fragment -> half the SMEM/LDSM traffic per unit work).
// Online softmax with UNMASKED running max (masked scores are finite, so a
// max over the superset is exact after post-exp zeroing of masked p).
#define FBM 128
#define FBN 64
#define FLD 72                 // half stride (144 B) -> conflict-free ldmatrix
#define FSTG (64*FLD)          // halfs per K (or V) tile
#define SCALE_LOG2E 0.180336879f   // 0.125 * log2(e)
#define MROW (S_/32)           // mask words per row

__global__ void __launch_bounds__(128, 2) flash3_kernel(
    const __half* __restrict__ Qp,
    const __half* __restrict__ Kp,
    const __half* __restrict__ Vp,
    const unsigned* __restrict__ maskbits,
    __half* __restrict__ ctx)
{
    __shared__ __half sm[2 * 2 * FSTG];   // [K0|V0|K1|V1] = 36864 B

    int tid  = threadIdx.x;
    int lane = tid & 31;
    int wid  = tid >> 5;       // 0..3
    int gr   = lane >> 2;      // row-in-16 group (rows gr and gr+8)
    int cc   = lane & 3;       // col pair selector

    int q0 = blockIdx.x * FBM;
    int bh = blockIdx.y;
    const __half* Qbase = Qp + ((size_t)bh * S_ + q0) * DK_;
    const __half* Kbase = Kp + (size_t)bh * S_ * DK_;
    const __half* Vbase = Vp + (size_t)bh * S_ * DK_;

    // ---- stage Q (128x64) through smem, ldmatrix into persistent A frags ----
    #pragma unroll
    for (int i = 0; i < 8; i++) {
        int c = tid + 128 * i;               // 0..1023
        int r = c >> 3, col = (c & 7) * 8;
        *(uint4*)&sm[r*FLD + col] = *(const uint4*)&Qbase[r*DK_ + col];
    }
    __syncthreads();

    unsigned qf[2][4][4];
    #pragma unroll
    for (int t = 0; t < 2; t++)
        #pragma unroll
        for (int kk = 0; kk < 4; kk++) {
            unsigned addr = smem_u32(
                &sm[(wid*32 + t*16 + (lane & 15))*FLD + (lane >> 4)*8 + kk*16]);
            ldsm_x4(qf[t][kk][0], qf[t][kk][1], qf[t][kk][2], qf[t][kk][3], addr);
        }
    __syncthreads();

    // ---- per-thread softmax state: t in {0,1} row-tiles, lo/hi row halves ----
    float o[2][8][4];
    #pragma unroll
    for (int t = 0; t < 2; t++)
        #pragma unroll
        for (int j = 0; j < 8; j++)
            { o[t][j][0]=0.f; o[t][j][1]=0.f; o[t][j][2]=0.f; o[t][j][3]=0.f; }
    float m_[2][2] = {{-1e30f,-1e30f},{-1e30f,-1e30f}};
    float l_[2][2] = {{0.f,0.f},{0.f,0.f}};

    const unsigned* mbase = maskbits + (size_t)(q0 + wid*32 + gr) * MROW;

    auto load_kv = [&](int j0, int s) {
        __half* Ks = sm + s * 2 * FSTG;
        __half* Vs = Ks + FSTG;
        #pragma unroll
        for (int i = 0; i < 4; i++) {
            int c = tid + 128 * i;           // 0..511
            int r = c >> 3, col = (c & 7) * 8;
            cp_async16(&Ks[r*FLD + col], &Kbase[(size_t)(j0 + r)*DK_ + col]);
        }
        #pragma unroll
        for (int i = 0; i < 4; i++) {
            int c = tid + 128 * i;
            int r = c >> 3, col = (c & 7) * 8;
            cp_async16(&Vs[r*FLD + col], &Vbase[(size_t)(j0 + r)*DK_ + col]);
        }
        CP_COMMIT();
    };

    load_kv(0, 0);

    for (int it = 0; it < S_/FBN; it++) {
        int j0 = it * FBN;
        CP_WAIT0();
        __syncthreads();
        if (it + 1 < S_/FBN) load_kv(j0 + FBN, (it + 1) & 1);

        const __half* Ks = sm + (it & 1) * 2 * FSTG;
        const __half* Vs = Ks + FSTG;

        // ---- S = Q K^T for both row-tiles, sharing B-frags ----
        float sc[2][8][4];
        #pragma unroll
        for (int t = 0; t < 2; t++)
            #pragma unroll
            for (int j = 0; j < 8; j++)
                { sc[t][j][0]=0.f; sc[t][j][1]=0.f; sc[t][j][2]=0.f; sc[t][j][3]=0.f; }
        #pragma unroll
        for (int j = 0; j < 8; j++) {
            #pragma unroll
            for (int kk = 0; kk < 4; kk += 2) {
                unsigned b0, b1, b2, b3;
                unsigned addr = smem_u32(&Ks[(j*8 + (lane & 7))*FLD + kk*16 + (lane >> 3)*8]);
                ldsm_x4(b0, b1, b2, b3, addr);
                mma16816(sc[0][j], qf[0][kk],   b0, b1);
                mma16816(sc[0][j], qf[0][kk+1], b2, b3);
                mma16816(sc[1][j], qf[1][kk],   b0, b1);
                mma16816(sc[1][j], qf[1][kk+1], b2, b3);
            }
        }

        // ---- softmax (unmasked max; mask applied post-exp) ----
        unsigned pl[2][8], ph[2][8];
        #pragma unroll
        for (int t = 0; t < 2; t++) {
            unsigned long long b64l = *(const unsigned long long*)(mbase + t*16*MROW + (j0 >> 5));
            unsigned long long b64h = *(const unsigned long long*)(mbase + (t*16+8)*MROW + (j0 >> 5));
            unsigned wl0 = (unsigned)b64l, wl1 = (unsigned)(b64l >> 32);
            unsigned wh0 = (unsigned)b64h, wh1 = (unsigned)(b64h >> 32);

            float mxl = -1e30f, mxh = -1e30f;
            #pragma unroll
            for (int j = 0; j < 8; j++) {
                mxl = fmaxf(mxl, fmaxf(sc[t][j][0], sc[t][j][1]));
                mxh = fmaxf(mxh, fmaxf(sc[t][j][2], sc[t][j][3]));
            }
            mxl = fmaxf(mxl, __shfl_xor_sync(0xffffffffu, mxl, 1));
            mxl = fmaxf(mxl, __shfl_xor_sync(0xffffffffu, mxl, 2));
            mxh = fmaxf(mxh, __shfl_xor_sync(0xffffffffu, mxh, 1));
            mxh = fmaxf(mxh, __shfl_xor_sync(0xffffffffu, mxh, 2));

            float mnl = fmaxf(m_[t][0], mxl * SCALE_LOG2E);
            float mnh = fmaxf(m_[t][1], mxh * SCALE_LOG2E);
            float al = exp2f(m_[t][0] - mnl), ah = exp2f(m_[t][1] - mnh);
            m_[t][0] = mnl; m_[t][1] = mnh;

            float sl = 0.f, sh = 0.f;
            #pragma unroll
            for (int j = 0; j < 8; j++) {
                int shamt = (j & 3)*8 + 2*cc;
                unsigned m2l = ((j < 4) ? wl0 : wl1) >> shamt;
                unsigned m2h = ((j < 4) ? wh0 : wh1) >> shamt;
                float p0 = exp2f(fmaf(sc[t][j][0], SCALE_LOG2E, -mnl));
                float p1 = exp2f(fmaf(sc[t][j][1], SCALE_LOG2E, -mnl));
                float p2 = exp2f(fmaf(sc[t][j][2], SCALE_LOG2E, -mnh));
                float p3 = exp2f(fmaf(sc[t][j][3], SCALE_LOG2E, -mnh));
                p0 = (m2l & 1u) ? p0 : 0.f;
                p1 = (m2l & 2u) ? p1 : 0.f;
                p2 = (m2h & 1u) ? p2 : 0.f;
                p3 = (m2h & 2u) ? p3 : 0.f;
                sl += p0 + p1; sh += p2 + p3;
                pl[t][j] = packh2(p0, p1);
                ph[t][j] = packh2(p2, p3);
            }
            sl += __shfl_xor_sync(0xffffffffu, sl, 1);
            sl += __shfl_xor_sync(0xffffffffu, sl, 2);
            sh += __shfl_xor_sync(0xffffffffu, sh, 1);
            sh += __shfl_xor_sync(0xffffffffu, sh, 2);
            l_[t][0] = l_[t][0] * al + sl;
            l_[t][1] = l_[t][1] * ah + sh;

            #pragma unroll
            for (int j = 0; j < 8; j++) {
                o[t][j][0] *= al; o[t][j][1] *= al;
                o[t][j][2] *= ah; o[t][j][3] *= ah;
            }
        }

        // ---- O += P V, sharing V B-frags between row-tiles ----
        #pragma unroll
        for (int jj = 0; jj < 4; jj++) {
            unsigned pa0[4] = { pl[0][2*jj], ph[0][2*jj], pl[0][2*jj+1], ph[0][2*jj+1] };
            unsigned pa1[4] = { pl[1][2*jj], ph[1][2*jj], pl[1][2*jj+1], ph[1][2*jj+1] };
            #pragma unroll
            for (int j = 0; j < 8; j += 2) {
                unsigned b0, b1, b2, b3;
                unsigned addr = smem_u32(&Vs[(jj*16 + (lane & 15))*FLD + j*8 + (lane >> 4)*8]);
                ldsm_x4t(b0, b1, b2, b3, addr);
                mma16816(o[0][j],   pa0, b0, b1);
                mma16816(o[0][j+1], pa0, b2, b3);
                mma16816(o[1][j],   pa1, b0, b1);
                mma16816(o[1][j+1], pa1, b2, b3);
            }
        }
    }

    // ---- epilogue: ctx[b, s, h*64+dk] = O / l ----
    int b = bh >> 4, h = bh & 15;
    #pragma unroll
    for (int t = 0; t < 2; t++) {
        float il = 1.f / l_[t][0], ih = 1.f / l_[t][1];
        int r = q0 + wid*32 + t*16 + gr;
        __half* dlo = ctx + ((size_t)(b * S_ + r)) * D_ + h * DK_;
        __half* dhi = dlo + (size_t)8 * D_;
        #pragma unroll
        for (int j = 0; j < 8; j++) {
            int cidx = j*8 + 2*cc;
            *(__half2*)&dlo[cidx] = __floats2half2_rn(o[t][j][0]*il, o[t][j][1]*il);
            *(__half2*)&dhi[cidx] = __floats2half2_rn(o[t][j][2]*ih, o[t][j][3]*ih);
        }
    }
}

// ---------------- launch ----------------
static void* symaddr(const void* sym) {
    void* p = nullptr;
    cudaGetSymbolAddress(&p, sym);
    return p;
}

extern "C" void kernel_launch(void* const* d_in, const int* in_sizes, int n_in,
                              void* d_out, int out_size)
{
    const float* q    = (const float*)d_in[0];
    const float* k    = (const float*)d_in[1];
    const float* v    = (const float*)d_in[2];
    const int*   mask = (const int*)  d_in[3];
    const float* w_q  = (const float*)d_in[4];
    const float* w_k  = (const float*)d_in[5];
    const float* w_v  = (const float*)d_in[6];
    const float* w_o  = (const float*)d_in[7];

    __half* qh = (__half*)symaddr(g_qh);
    __half* kh = (__half*)symaddr(g_kh);
    __half* vh = (__half*)symaddr(g_vh);
    __half* wq = (__half*)symaddr(g_wq);
    __half* wk = (__half*)symaddr(g_wk);
    __half* wv = (__half*)symaddr(g_wv);
    __half* wo = (__half*)symaddr(g_wo);
    __half* Qp = (__half*)symaddr(g_Q);
    __half* Kp = (__half*)symaddr(g_K);
    __half* Vp = (__half*)symaddr(g_V);
    __half* cx = (__half*)symaddr(g_ctx);
    unsigned* mb = (unsigned*)symaddr(g_maskbits);

    // fused converts (1 launch): q,k,v then the 4 weights
    {
        dim3 cg(BS_*D_/4/256, 7);
        f2h_multi_kernel<<<cg, 256>>>(
            (const float4*)q, (const float4*)k, (const float4*)v,
            (const float4*)w_q, (const float4*)w_k, (const float4*)w_v, (const float4*)w_o,
            (__half2*)qh, (__half2*)kh, (__half2*)vh,
            (__half2*)wq, (__half2*)wk, (__half2*)wv, (__half2*)wo);
    }

    // mask bitpack
    maskpack_kernel<<<(S_*S_)/256, 256>>>(mask, mb, S_*S_);

    // projections -> head-major Q/K/V (fused single launch)
    cudaFuncSetAttribute(gemm_qkv_kernel, cudaFuncAttributeMaxDynamicSharedMemorySize, G2_SMEM);
    cudaFuncSetAttribute(gemm_out_kernel, cudaFuncAttributeMaxDynamicSharedMemorySize, G2_SMEM);
    dim3 gq(D_/128, BS_/128, 3);
    gemm_qkv_kernel<<<gq, 256, G2_SMEM>>>(qh, kh, vh, wq, wk, wv, Qp, Kp, Vp);

    // flash attention v3 (32 rows/warp)
    flash3_kernel<<<dim3(S_/FBM, B_*H_), 128>>>(Qp, Kp, Vp, mb, cx);

    // output projection (fp32 out)
    dim3 gg(D_/128, BS_/128);
    gemm_out_kernel<<<gg, 256, G2_SMEM>>>(cx, wo, (float*)d_out);
}

// round 7
// speedup vs baseline: 2.5349x; 1.1145x over previous
#include <cuda_runtime.h>
#include <cuda_fp16.h>
#include <cstdint>

#define B_  2
#define S_  4096
#define D_  1024
#define H_  16
#define DK_ 64
#define BS_ (B_*S_)          // 8192 rows

// ---------------- device scratch (static, no allocations) ----------------
__device__ __half g_qh[BS_*D_];
__device__ __half g_kh[BS_*D_];
__device__ __half g_vh[BS_*D_];
__device__ __half g_wq[D_*D_];
__device__ __half g_wk[D_*D_];
__device__ __half g_wv[D_*D_];
__device__ __half g_wo[D_*D_];
__device__ __half g_Q[BS_*D_];    // [B,H,S,DK]
__device__ __half g_K[BS_*D_];    // [B,H,S,DK]
__device__ __half g_V[BS_*D_];    // [B,H,S,DK]
__device__ __half g_ctx[BS_*D_];  // [B,S,D]
__device__ unsigned g_maskbits[S_*S_/32];

// ---------------- small PTX helpers ----------------
__device__ __forceinline__ unsigned smem_u32(const void* p) {
    return (unsigned)__cvta_generic_to_shared(p);
}
__device__ __forceinline__ void cp_async16(void* dst, const void* src) {
    asm volatile("cp.async.cg.shared.global [%0], [%1], 16;"
                 :: "r"(smem_u32(dst)), "l"(src));
}
#define CP_COMMIT() asm volatile("cp.async.commit_group;")
#define CP_WAIT0()  asm volatile("cp.async.wait_group 0;")

__device__ __forceinline__ void ldsm_x4(unsigned& r0, unsigned& r1, unsigned& r2, unsigned& r3,
                                        unsigned a) {
    asm volatile("ldmatrix.sync.aligned.m8n8.x4.shared.b16 {%0,%1,%2,%3},[%4];"
                 : "=r"(r0), "=r"(r1), "=r"(r2), "=r"(r3) : "r"(a));
}
__device__ __forceinline__ void ldsm_x4t(unsigned& r0, unsigned& r1, unsigned& r2, unsigned& r3,
                                         unsigned a) {
    asm volatile("ldmatrix.sync.aligned.m8n8.x4.trans.shared.b16 {%0,%1,%2,%3},[%4];"
                 : "=r"(r0), "=r"(r1), "=r"(r2), "=r"(r3) : "r"(a));
}
__device__ __forceinline__ void mma16816(float* c, const unsigned a[4], unsigned b0, unsigned b1) {
    asm volatile("mma.sync.aligned.m16n8k16.row.col.f32.f16.f16.f32 "
                 "{%0,%1,%2,%3},{%4,%5,%6,%7},{%8,%9},{%0,%1,%2,%3};"
                 : "+f"(c[0]), "+f"(c[1]), "+f"(c[2]), "+f"(c[3])
                 : "r"(a[0]), "r"(a[1]), "r"(a[2]), "r"(a[3]), "r"(b0), "r"(b1));
}
// pack two f32 into half2 (lo, hi), then 2^x on both halves with one MUFU op
__device__ __forceinline__ unsigned cvt_h2(float lo, float hi) {
    unsigned r;
    asm("cvt.rn.f16x2.f32 %0, %1, %2;" : "=r"(r) : "f"(hi), "f"(lo));
    return r;
}
__device__ __forceinline__ unsigned h2exp2(unsigned t) {
    unsigned r;
    asm("ex2.approx.f16x2 %0, %1;" : "=r"(r) : "r"(t));
    return r;
}

// ---------------- fused fp32 -> fp16 convert (7 tensors, one launch) ----------------
__global__ void f2h_multi_kernel(
    const float4* __restrict__ s0, const float4* __restrict__ s1,
    const float4* __restrict__ s2, const float4* __restrict__ s3,
    const float4* __restrict__ s4, const float4* __restrict__ s5,
    const float4* __restrict__ s6,
    __half2* __restrict__ d0, __half2* __restrict__ d1,
    __half2* __restrict__ d2, __half2* __restrict__ d3,
    __half2* __restrict__ d4, __half2* __restrict__ d5,
    __half2* __restrict__ d6)
{
    int t = blockIdx.y;
    const float4* src; __half2* dst; int n4;
    switch (t) {
        case 0: src = s0; dst = d0; n4 = BS_*D_/4; break;
        case 1: src = s1; dst = d1; n4 = BS_*D_/4; break;
        case 2: src = s2; dst = d2; n4 = BS_*D_/4; break;
        case 3: src = s3; dst = d3; n4 = D_*D_/4; break;
        case 4: src = s4; dst = d4; n4 = D_*D_/4; break;
        case 5: src = s5; dst = d5; n4 = D_*D_/4; break;
        default: src = s6; dst = d6; n4 = D_*D_/4; break;
    }
    int i = blockIdx.x * blockDim.x + threadIdx.x;
    if (i < n4) {
        float4 v = src[i];
        dst[2*i + 0] = __floats2half2_rn(v.x, v.y);
        dst[2*i + 1] = __floats2half2_rn(v.z, v.w);
    }
}

// ---------------- mask -> bitmask ----------------
__global__ void maskpack_kernel(const int* __restrict__ mask, unsigned* __restrict__ out, int n) {
    int i = blockIdx.x * blockDim.x + threadIdx.x;
    unsigned b = __ballot_sync(0xffffffffu, (i < n) && (mask[i] != 0));
    if (((threadIdx.x & 31) == 0) && i < n) out[i >> 5] = b;
}

// ---------------- GEMM v2: raw mma.sync, C[M,1024] = A[M,1024] * W[1024,1024]^T --------
#define G2_LD   72                      // half stride (144 B)
#define G2_TILE (128*G2_LD)             // halfs per A (or B) tile
#define G2_SMEM (2*2*G2_TILE*2)         // bytes: 2 stages x (A+B) = 73728

template <bool HEAD_OUT>
__device__ __forceinline__ void gemm2_core(
    const __half* __restrict__ A,
    const __half* __restrict__ W,
    __half* __restrict__ outH,
    float* __restrict__ outF,
    __half* gsm, int bm, int bn)
{
    int tid  = threadIdx.x;
    int lane = tid & 31;
    int wid  = tid >> 5;
    int warp_m = wid >> 1;       // 0..3 -> 32 rows
    int warp_n = wid & 1;        // 0..1 -> 64 cols
    int gr = lane >> 2;          // 0..7
    int cc = lane & 3;

    float c[2][8][4];
    #pragma unroll
    for (int i = 0; i < 2; i++)
        #pragma unroll
        for (int j = 0; j < 8; j++)
            { c[i][j][0]=0.f; c[i][j][1]=0.f; c[i][j][2]=0.f; c[i][j][3]=0.f; }

    auto load_stage = [&](int chunk, int s) {
        __half* As = gsm + s * 2 * G2_TILE;
        __half* Bs = As + G2_TILE;
        int k0 = chunk * 64;
        #pragma unroll
        for (int i = 0; i < 4; i++) {
            int idx = tid + 256 * i;             // 0..1023
            int r = idx >> 3, col = (idx & 7) * 8;
            cp_async16(&As[r*G2_LD + col], &A[(size_t)(bm + r) * 1024 + k0 + col]);
        }
        #pragma unroll
        for (int i = 0; i < 4; i++) {
            int idx = tid + 256 * i;
            int r = idx >> 3, col = (idx & 7) * 8;
            cp_async16(&Bs[r*G2_LD + col], &W[(size_t)(bn + r) * 1024 + k0 + col]);
        }
        CP_COMMIT();
    };

    load_stage(0, 0);

    for (int it = 0; it < 16; it++) {
        CP_WAIT0();
        __syncthreads();
        if (it < 15) load_stage(it + 1, (it + 1) & 1);

        const __half* As = gsm + (it & 1) * 2 * G2_TILE;
        const __half* Bs = As + G2_TILE;

        #pragma unroll
        for (int kk = 0; kk < 4; kk += 2) {
            unsigned a[2][2][4];
            #pragma unroll
            for (int t = 0; t < 2; t++)
                #pragma unroll
                for (int i = 0; i < 2; i++) {
                    unsigned addr = smem_u32(
                        &As[(warp_m*32 + i*16 + (lane & 15))*G2_LD + (kk + t)*16 + (lane >> 4)*8]);
                    ldsm_x4(a[t][i][0], a[t][i][1], a[t][i][2], a[t][i][3], addr);
                }
            #pragma unroll
            for (int j = 0; j < 8; j++) {
                unsigned b0, b1, b2, b3;
                unsigned addr = smem_u32(
                    &Bs[(warp_n*64 + j*8 + (lane & 7))*G2_LD + kk*16 + (lane >> 3)*8]);
                ldsm_x4(b0, b1, b2, b3, addr);
                mma16816(c[0][j], a[0][0], b0, b1);
                mma16816(c[1][j], a[0][1], b0, b1);
                mma16816(c[0][j], a[1][0], b2, b3);
                mma16816(c[1][j], a[1][1], b2, b3);
            }
        }
        __syncthreads();
    }

    // ---- epilogue: direct global writes from accumulators ----
    if (HEAD_OUT) {
        int e0 = bn + warp_n * 64;              // 64-aligned -> single head per warp
        int h = e0 >> 6;
        #pragma unroll
        for (int i = 0; i < 2; i++) {
            int m0 = bm + warp_m*32 + i*16 + gr;
            int b = m0 >> 12, s0 = m0 & 4095;
            __half* dst0 = outH + ((size_t)(b*H_ + h) * S_ + s0) * DK_;
            __half* dst1 = dst0 + (size_t)8 * DK_;
            #pragma unroll
            for (int j = 0; j < 8; j++) {
                int col = j*8 + 2*cc;
                *(__half2*)&dst0[col] = __floats2half2_rn(c[i][j][0], c[i][j][1]);
                *(__half2*)&dst1[col] = __floats2half2_rn(c[i][j][2], c[i][j][3]);
            }
        }
    } else {
        int e0 = bn + warp_n * 64;
        #pragma unroll
        for (int i = 0; i < 2; i++) {
            int m0 = bm + warp_m*32 + i*16 + gr;
            float* dst0 = outF + (size_t)m0 * 1024 + e0;
            float* dst1 = dst0 + (size_t)8 * 1024;
            #pragma unroll
            for (int j = 0; j < 8; j++) {
                int col = j*8 + 2*cc;
                *(float2*)&dst0[col] = make_float2(c[i][j][0], c[i][j][1]);
                *(float2*)&dst1[col] = make_float2(c[i][j][2], c[i][j][3]);
            }
        }
    }
}

__global__ void __launch_bounds__(256, 2) gemm_qkv_kernel(
    const __half* __restrict__ a0, const __half* __restrict__ a1, const __half* __restrict__ a2,
    const __half* __restrict__ w0, const __half* __restrict__ w1, const __half* __restrict__ w2,
    __half* __restrict__ o0, __half* __restrict__ o1, __half* __restrict__ o2)
{
    extern __shared__ __half gsm[];
    const __half* A; const __half* W; __half* O;
    if (blockIdx.z == 0)      { A = a0; W = w0; O = o0; }
    else if (blockIdx.z == 1) { A = a1; W = w1; O = o1; }
    else                      { A = a2; W = w2; O = o2; }
    gemm2_core<true>(A, W, O, nullptr, gsm, blockIdx.y * 128, blockIdx.x * 128);
}

__global__ void __launch_bounds__(256, 2) gemm_out_kernel(
    const __half* __restrict__ A, const __half* __restrict__ W, float* __restrict__ outF)
{
    extern __shared__ __half gsm[];
    gemm2_core<false>(A, W, nullptr, outF, gsm, blockIdx.y * 128, blockIdx.x * 128);
}

// ---------------- Flash attention v4: f16x2 exp, ones-MMA row sums, mask prefetch ----
#define FBM 128
#define FBN 64
#define FLD 72                 // half stride (144 B) -> conflict-free ldmatrix
#define FSTG (64*FLD)          // halfs per K (or V) tile
#define SCALE_LOG2E 0.180336879f   // 0.125 * log2(e)
#define MROW (S_/32)           // mask words per row
#define ONES_H2 0x3C003C00u    // half2(1.0, 1.0)

__global__ void __launch_bounds__(128, 2) flash4_kernel(
    const __half* __restrict__ Qp,
    const __half* __restrict__ Kp,
    const __half* __restrict__ Vp,
    const unsigned* __restrict__ maskbits,
    __half* __restrict__ ctx)
{
    __shared__ __half sm[2 * 2 * FSTG];   // [K0|V0|K1|V1] = 36864 B

    int tid  = threadIdx.x;
    int lane = tid & 31;
    int wid  = tid >> 5;       // 0..3
    int gr   = lane >> 2;      // row-in-16 group (rows gr and gr+8)
    int cc   = lane & 3;       // col pair selector

    int q0 = blockIdx.x * FBM;
    int bh = blockIdx.y;
    const __half* Qbase = Qp + ((size_t)bh * S_ + q0) * DK_;
    const __half* Kbase = Kp + (size_t)bh * S_ * DK_;
    const __half* Vbase = Vp + (size_t)bh * S_ * DK_;

    // ---- stage Q (128x64) through smem, ldmatrix into persistent A frags ----
    #pragma unroll
    for (int i = 0; i < 8; i++) {
        int c = tid + 128 * i;               // 0..1023
        int r = c >> 3, col = (c & 7) * 8;
        *(uint4*)&sm[r*FLD + col] = *(const uint4*)&Qbase[r*DK_ + col];
    }
    __syncthreads();

    unsigned qf[2][4][4];
    #pragma unroll
    for (int t = 0; t < 2; t++)
        #pragma unroll
        for (int kk = 0; kk < 4; kk++) {
            unsigned addr = smem_u32(
                &sm[(wid*32 + t*16 + (lane & 15))*FLD + (lane >> 4)*8 + kk*16]);
            ldsm_x4(qf[t][kk][0], qf[t][kk][1], qf[t][kk][2], qf[t][kk][3], addr);
        }
    __syncthreads();

    float o[2][8][4];
    #pragma unroll
    for (int t = 0; t < 2; t++)
        #pragma unroll
        for (int j = 0; j < 8; j++)
            { o[t][j][0]=0.f; o[t][j][1]=0.f; o[t][j][2]=0.f; o[t][j][3]=0.f; }
    float m_[2][2] = {{-1e30f,-1e30f},{-1e30f,-1e30f}};
    float l_[2][2] = {{0.f,0.f},{0.f,0.f}};

    const unsigned* mbase = maskbits + (size_t)(q0 + wid*32 + gr) * MROW;

    auto load_kv = [&](int j0, int s) {
        __half* Ks = sm + s * 2 * FSTG;
        __half* Vs = Ks + FSTG;
        #pragma unroll
        for (int i = 0; i < 4; i++) {
            int c = tid + 128 * i;           // 0..511
            int r = c >> 3, col = (c & 7) * 8;
            cp_async16(&Ks[r*FLD + col], &Kbase[(size_t)(j0 + r)*DK_ + col]);
        }
        #pragma unroll
        for (int i = 0; i < 4; i++) {
            int c = tid + 128 * i;
            int r = c >> 3, col = (c & 7) * 8;
            cp_async16(&Vs[r*FLD + col], &Vbase[(size_t)(j0 + r)*DK_ + col]);
        }
        CP_COMMIT();
    };

    load_kv(0, 0);

    // mask prefetch for tile 0
    unsigned long long nmask[2][2];
    #pragma unroll
    for (int t = 0; t < 2; t++) {
        nmask[t][0] = *(const unsigned long long*)(mbase + t*16*MROW);
        nmask[t][1] = *(const unsigned long long*)(mbase + (t*16+8)*MROW);
    }

    for (int it = 0; it < S_/FBN; it++) {
        int j0 = it * FBN;
        CP_WAIT0();
        __syncthreads();
        if (it + 1 < S_/FBN) load_kv(j0 + FBN, (it + 1) & 1);

        const __half* Ks = sm + (it & 1) * 2 * FSTG;
        const __half* Vs = Ks + FSTG;

        // consume prefetched masks; prefetch next tile's
        unsigned long long cmask[2][2] = {{nmask[0][0], nmask[0][1]},
                                          {nmask[1][0], nmask[1][1]}};
        if (it + 1 < S_/FBN) {
            int w = (j0 + FBN) >> 5;
            #pragma unroll
            for (int t = 0; t < 2; t++) {
                nmask[t][0] = *(const unsigned long long*)(mbase + t*16*MROW + w);
                nmask[t][1] = *(const unsigned long long*)(mbase + (t*16+8)*MROW + w);
            }
        }

        // ---- S = Q K^T for both row-tiles, sharing B-frags ----
        float sc[2][8][4];
        #pragma unroll
        for (int t = 0; t < 2; t++)
            #pragma unroll
            for (int j = 0; j < 8; j++)
                { sc[t][j][0]=0.f; sc[t][j][1]=0.f; sc[t][j][2]=0.f; sc[t][j][3]=0.f; }
        #pragma unroll
        for (int j = 0; j < 8; j++) {
            #pragma unroll
            for (int kk = 0; kk < 4; kk += 2) {
                unsigned b0, b1, b2, b3;
                unsigned addr = smem_u32(&Ks[(j*8 + (lane & 7))*FLD + kk*16 + (lane >> 3)*8]);
                ldsm_x4(b0, b1, b2, b3, addr);
                mma16816(sc[0][j], qf[0][kk],   b0, b1);
                mma16816(sc[0][j], qf[0][kk+1], b2, b3);
                mma16816(sc[1][j], qf[1][kk],   b0, b1);
                mma16816(sc[1][j], qf[1][kk+1], b2, b3);
            }
        }

        // ---- softmax: unmasked max, fp16x2 exp, mask as SEL to -64 ----
        unsigned pl[2][8], ph[2][8];
        #pragma unroll
        for (int t = 0; t < 2; t++) {
            unsigned wl0 = (unsigned)cmask[t][0], wl1 = (unsigned)(cmask[t][0] >> 32);
            unsigned wh0 = (unsigned)cmask[t][1], wh1 = (unsigned)(cmask[t][1] >> 32);

            float mxl = -1e30f, mxh = -1e30f;
            #pragma unroll
            for (int j = 0; j < 8; j++) {
                mxl = fmaxf(mxl, fmaxf(sc[t][j][0], sc[t][j][1]));
                mxh = fmaxf(mxh, fmaxf(sc[t][j][2], sc[t][j][3]));
            }
            mxl = fmaxf(mxl, __shfl_xor_sync(0xffffffffu, mxl, 1));
            mxl = fmaxf(mxl, __shfl_xor_sync(0xffffffffu, mxl, 2));
            mxh = fmaxf(mxh, __shfl_xor_sync(0xffffffffu, mxh, 1));
            mxh = fmaxf(mxh, __shfl_xor_sync(0xffffffffu, mxh, 2));

            float mnl = fmaxf(m_[t][0], mxl * SCALE_LOG2E);
            float mnh = fmaxf(m_[t][1], mxh * SCALE_LOG2E);
            float al = exp2f(m_[t][0] - mnl), ah = exp2f(m_[t][1] - mnh);
            m_[t][0] = mnl; m_[t][1] = mnh;

            #pragma unroll
            for (int j = 0; j < 8; j++) {
                int shamt = (j & 3)*8 + 2*cc;
                unsigned m2l = ((j < 4) ? wl0 : wl1) >> shamt;
                unsigned m2h = ((j < 4) ? wh0 : wh1) >> shamt;
                float t0 = fmaf(sc[t][j][0], SCALE_LOG2E, -mnl);
                float t1 = fmaf(sc[t][j][1], SCALE_LOG2E, -mnl);
                float t2 = fmaf(sc[t][j][2], SCALE_LOG2E, -mnh);
                float t3 = fmaf(sc[t][j][3], SCALE_LOG2E, -mnh);
                t0 = (m2l & 1u) ? t0 : -64.f;
                t1 = (m2l & 2u) ? t1 : -64.f;
                t2 = (m2h & 1u) ? t2 : -64.f;
                t3 = (m2h & 2u) ? t3 : -64.f;
                pl[t][j] = h2exp2(cvt_h2(t0, t1));
                ph[t][j] = h2exp2(cvt_h2(t2, t3));
            }

            // row sums via ones-MMA: lanes get rowsum(gr) in [0], rowsum(gr+8) in [2]
            float la[4] = {0.f, 0.f, 0.f, 0.f};
            #pragma unroll
            for (int jj = 0; jj < 4; jj++) {
                unsigned pa[4] = { pl[t][2*jj], ph[t][2*jj], pl[t][2*jj+1], ph[t][2*jj+1] };
                mma16816(la, pa, ONES_H2, ONES_H2);
            }
            l_[t][0] = l_[t][0] * al + la[0];
            l_[t][1] = l_[t][1] * ah + la[2];

            #pragma unroll
            for (int j = 0; j < 8; j++) {
                o[t][j][0] *= al; o[t][j][1] *= al;
                o[t][j][2] *= ah; o[t][j][3] *= ah;
            }
        }

        // ---- O += P V, sharing V B-frags between row-tiles ----
        #pragma unroll
        for (int jj = 0; jj < 4; jj++) {
            unsigned pa0[4] = { pl[0][2*jj], ph[0][2*jj], pl[0][2*jj+1], ph[0][2*jj+1] };
            unsigned pa1[4] = { pl[1][2*jj], ph[1][2*jj], pl[1][2*jj+1], ph[1][2*jj+1] };
            #pragma unroll
            for (int j = 0; j < 8; j += 2) {
                unsigned b0, b1, b2, b3;
                unsigned addr = smem_u32(&Vs[(jj*16 + (lane & 15))*FLD + j*8 + (lane >> 4)*8]);
                ldsm_x4t(b0, b1, b2, b3, addr);
                mma16816(o[0][j],   pa0, b0, b1);
                mma16816(o[0][j+1], pa0, b2, b3);
                mma16816(o[1][j],   pa1, b0, b1);
                mma16816(o[1][j+1], pa1, b2, b3);
            }
        }
    }

    // ---- epilogue: ctx[b, s, h*64+dk] = O / l ----
    int b = bh >> 4, h = bh & 15;
    #pragma unroll
    for (int t = 0; t < 2; t++) {
        float il = 1.f / l_[t][0], ih = 1.f / l_[t][1];
        int r = q0 + wid*32 + t*16 + gr;
        __half* dlo = ctx + ((size_t)(b * S_ + r)) * D_ + h * DK_;
        __half* dhi = dlo + (size_t)8 * D_;
        #pragma unroll
        for (int j = 0; j < 8; j++) {
            int cidx = j*8 + 2*cc;
            *(__half2*)&dlo[cidx] = __floats2half2_rn(o[t][j][0]*il, o[t][j][1]*il);
            *(__half2*)&dhi[cidx] = __floats2half2_rn(o[t][j][2]*ih, o[t][j][3]*ih);
        }
    }
}

// ---------------- launch ----------------
static void* symaddr(const void* sym) {
    void* p = nullptr;
    cudaGetSymbolAddress(&p, sym);
    return p;
}

extern "C" void kernel_launch(void* const* d_in, const int* in_sizes, int n_in,
                              void* d_out, int out_size)
{
    const float* q    = (const float*)d_in[0];
    const float* k    = (const float*)d_in[1];
    const float* v    = (const float*)d_in[2];
    const int*   mask = (const int*)  d_in[3];
    const float* w_q  = (const float*)d_in[4];
    const float* w_k  = (const float*)d_in[5];
    const float* w_v  = (const float*)d_in[6];
    const float* w_o  = (const float*)d_in[7];

    __half* qh = (__half*)symaddr(g_qh);
    __half* kh = (__half*)symaddr(g_kh);
    __half* vh = (__half*)symaddr(g_vh);
    __half* wq = (__half*)symaddr(g_wq);
    __half* wk = (__half*)symaddr(g_wk);
    __half* wv = (__half*)symaddr(g_wv);
    __half* wo = (__half*)symaddr(g_wo);
    __half* Qp = (__half*)symaddr(g_Q);
    __half* Kp = (__half*)symaddr(g_K);
    __half* Vp = (__half*)symaddr(g_V);
    __half* cx = (__half*)symaddr(g_ctx);
    unsigned* mb = (unsigned*)symaddr(g_maskbits);

    // fused converts (1 launch): q,k,v then the 4 weights
    {
        dim3 cg(BS_*D_/4/256, 7);
        f2h_multi_kernel<<<cg, 256>>>(
            (const float4*)q, (const float4*)k, (const float4*)v,
            (const float4*)w_q, (const float4*)w_k, (const float4*)w_v, (const float4*)w_o,
            (__half2*)qh, (__half2*)kh, (__half2*)vh,
            (__half2*)wq, (__half2*)wk, (__half2*)wv, (__half2*)wo);
    }

    // mask bitpack
    maskpack_kernel<<<(S_*S_)/256, 256>>>(mask, mb, S_*S_);

    // projections -> head-major Q/K/V (fused single launch)
    cudaFuncSetAttribute(gemm_qkv_kernel, cudaFuncAttributeMaxDynamicSharedMemorySize, G2_SMEM);
    cudaFuncSetAttribute(gemm_out_kernel, cudaFuncAttributeMaxDynamicSharedMemorySize, G2_SMEM);
    dim3 gq(D_/128, BS_/128, 3);
    gemm_qkv_kernel<<<gq, 256, G2_SMEM>>>(qh, kh, vh, wq, wk, wv, Qp, Kp, Vp);

    // flash attention v4
    flash4_kernel<<<dim3(S_/FBM, B_*H_), 128>>>(Qp, Kp, Vp, mb, cx);

    // output projection (fp32 out)
    dim3 gg(D_/128, BS_/128);
    gemm_out_kernel<<<gg, 256, G2_SMEM>>>(cx, wo, (float*)d_out);
}